// round 13
// baseline (speedup 1.0000x reference)
#include <cuda_runtime.h>
#include <cuda_bf16.h>
#include <math.h>
#include <stdint.h>

// Problem constants
#define L 2048
#define S 2048
#define E 2048
#define H 16
#define D 128
#define SCALE 0.08838834764831843f      // 1/sqrt(128)
#define LOG2E 1.4426950408889634f
#define SCALE2 (SCALE * LOG2E)          // scale in base-2 domain

typedef __nv_bfloat16 bf16;

// ---------------- scratch (static device globals; no allocation) -------------
__device__ bf16  g_in3[3L * L * E];          // q,k,v inputs (bf16), stacked
__device__ bf16  g_wb[3L * E * E];           // in_proj weights bf16
__device__ bf16  g_owb[(long)E * E];         // out_proj weights bf16
__device__ bf16  g_QKV[3L * L * E];          // Q | K | V (each [L,E])
__device__ bf16  g_ctxb[(long)L * E];
__device__ float g_tb[H * S];                // time bias PRE-SCALED by log2(e)
__device__ float g_x[(long)L * E];

// ---------------- ptx helpers ------------------------------------------------
__device__ __forceinline__ uint32_t pack_bf16(float x, float y) {
    uint32_t u;
    asm("cvt.rn.bf16x2.f32 %0, %1, %2;" : "=r"(u) : "f"(y), "f"(x));
    return u;
}

__device__ __forceinline__ float ex2(float x) {
    float r;
    asm("ex2.approx.f32 %0, %1;" : "=f"(r) : "f"(x));
    return r;
}

__device__ __forceinline__ void mma_bf16(float c[4],
                                         uint32_t a0, uint32_t a1, uint32_t a2, uint32_t a3,
                                         uint32_t b0, uint32_t b1) {
    asm volatile(
        "mma.sync.aligned.m16n8k16.row.col.f32.bf16.bf16.f32 "
        "{%0,%1,%2,%3}, {%4,%5,%6,%7}, {%8,%9}, {%0,%1,%2,%3};\n"
        : "+f"(c[0]), "+f"(c[1]), "+f"(c[2]), "+f"(c[3])
        : "r"(a0), "r"(a1), "r"(a2), "r"(a3), "r"(b0), "r"(b1));
}

__device__ __forceinline__ void cp16(uint32_t dst, const void* src) {
    asm volatile("cp.async.cg.shared.global [%0], [%1], 16;" :: "r"(dst), "l"(src));
}
#define CP_COMMIT() asm volatile("cp.async.commit_group;")
#define CP_WAIT1()  asm volatile("cp.async.wait_group 1;")
#define CP_WAIT0()  asm volatile("cp.async.wait_group 0;")

#define LDSM4(r0, r1, r2, r3, addr)                                            \
    asm volatile("ldmatrix.sync.aligned.m8n8.x4.shared.b16 {%0,%1,%2,%3}, [%4];" \
                 : "=r"(r0), "=r"(r1), "=r"(r2), "=r"(r3) : "r"(addr))
#define LDSM4T(r0, r1, r2, r3, addr)                                           \
    asm volatile("ldmatrix.sync.aligned.m8n8.x4.trans.shared.b16 {%0,%1,%2,%3}, [%4];" \
                 : "=r"(r0), "=r"(r1), "=r"(r2), "=r"(r3) : "r"(addr))

__device__ __forceinline__ float warpReduceSum(float v) {
    #pragma unroll
    for (int o = 16; o > 0; o >>= 1) v += __shfl_xor_sync(0xffffffffu, v, o);
    return v;
}
template<bool MAX>
__device__ __forceinline__ float blockReduce256(float v) {
    __shared__ float sh[8];
    int lane = threadIdx.x & 31, wid = threadIdx.x >> 5;
    #pragma unroll
    for (int o = 16; o > 0; o >>= 1)
        v = MAX ? fmaxf(v, __shfl_xor_sync(0xffffffffu, v, o))
                : v + __shfl_xor_sync(0xffffffffu, v, o);
    if (lane == 0) sh[wid] = v;
    __syncthreads();
    if (wid == 0) {
        float t = (lane < 8) ? sh[lane] : (MAX ? -INFINITY : 0.0f);
        #pragma unroll
        for (int o = 4; o > 0; o >>= 1)
            t = MAX ? fmaxf(t, __shfl_xor_sync(0xffffffffu, t, o))
                    : t + __shfl_xor_sync(0xffffffffu, t, o);
        if (lane == 0) sh[0] = t;
    }
    __syncthreads();
    float r = sh[0];
    __syncthreads();
    return r;
}

// ---------------- batched fp32 -> bf16 conversion (exact-sized 1D grid) ------
struct CvtJobs {
    const float4* in[5];
    uint2*        out[5];
    int           n4[5];
    int           off[6];   // block offsets, off[5] = total blocks
};

__global__ __launch_bounds__(256) void cvt_multi(CvtJobs jobs)
{
    int b = blockIdx.x;
    int z = 0;
    #pragma unroll
    for (int k = 1; k < 5; k++) z += (b >= jobs.off[k]);
    const float4* __restrict__ in = jobs.in[z];
    uint2* __restrict__ out = jobs.out[z];
    const int n4 = jobs.n4[z];
    int i0 = (b - jobs.off[z]) * 1024 + threadIdx.x;
    float4 v[4];
    #pragma unroll
    for (int j = 0; j < 4; j++) {
        int i = i0 + j * 256;
        if (i < n4) v[j] = in[i];
    }
    #pragma unroll
    for (int j = 0; j < 4; j++) {
        int i = i0 + j * 256;
        if (i < n4)
            out[i] = make_uint2(pack_bf16(v[j].x, v[j].y), pack_bf16(v[j].z, v[j].w));
    }
}

// ================= mma.sync NT GEMM (R6/R8 proven config) ====================
#define BM 128
#define BN 128
#define BKq 32
#define STAGE_BYTES 16384

__global__ __launch_bounds__(256, 2) void bgemm_nt(
    const bf16* __restrict__ A, const bf16* __restrict__ B,
    float* __restrict__ C, bf16* __restrict__ Cb,
    int K, int lda, int ldb, int ldc,
    long aZ, long bZ, long cZ,
    const float* __restrict__ bias, long biasZ,
    const float* __restrict__ res, int ldr,
    float scale)
{
    const int z = blockIdx.z;
    A += (long)z * aZ;
    B += (long)z * bZ;
    if (C)  C  += (long)z * cZ;
    if (Cb) Cb += (long)z * cZ;
    if (bias) bias += (long)z * biasZ;

    __shared__ __align__(16) unsigned char sm[3 * STAGE_BYTES];
    const uint32_t smBase = (uint32_t)__cvta_generic_to_shared(sm);

    const int tid  = threadIdx.x;
    const int wid  = tid >> 5;
    const int lane = tid & 31;
    const int wm = (wid & 1) * 64;
    const int wn = (wid >> 1) * 32;

    const long m0g = (long)blockIdx.y * BM;
    const long n0g = (long)blockIdx.x * BN;

    const int rowA = tid >> 2;
    const int cA   = tid & 3;
    const uint32_t aOff = rowA * 64 + ((cA ^ ((rowA >> 1) & 3)) * 16);
    const bf16* gA0 = A + (m0g + rowA) * (long)lda + cA * 8;
    const bf16* gA1 = gA0 + 64 * (long)lda;
    const bf16* gB0 = B + (n0g + rowA) * (long)ldb + cA * 8;
    const bf16* gB1 = gB0 + 64 * (long)ldb;

    auto ldg = [&](int st, int k0) {
        uint32_t aSt = smBase + st * STAGE_BYTES;
        uint32_t bSt = aSt + 8192;
        cp16(aSt + aOff,        gA0 + k0);
        cp16(aSt + aOff + 4096, gA1 + k0);
        cp16(bSt + aOff,        gB0 + k0);
        cp16(bSt + aOff + 4096, gB1 + k0);
        CP_COMMIT();
    };

    const int q = lane >> 3, r = lane & 7;
    const int aRowBase = wm + ((q & 1) << 3) + r;
    const int pa = (aRowBase >> 1) & 3;
    const int bRowBase = wn + ((q >> 1) << 3) + r;
    const int pb = (bRowBase >> 1) & 3;

    float acc[4][4][4];
    #pragma unroll
    for (int i = 0; i < 4; i++)
        #pragma unroll
        for (int j = 0; j < 4; j++)
            #pragma unroll
            for (int t = 0; t < 4; t++) acc[i][j][t] = 0.0f;

    auto compute = [&](int st) {
        uint32_t aSt = smBase + st * STAGE_BYTES;
        uint32_t bSt = aSt + 8192;
        #pragma unroll
        for (int ks = 0; ks < 2; ks++) {
            uint32_t a[4][4];
            #pragma unroll
            for (int mt = 0; mt < 4; mt++) {
                uint32_t addr = aSt + (aRowBase + mt * 16) * 64 +
                                (((ks * 2 + (q >> 1)) ^ pa) * 16);
                LDSM4(a[mt][0], a[mt][1], a[mt][2], a[mt][3], addr);
            }
            uint32_t b[4][2];
            #pragma unroll
            for (int ntp = 0; ntp < 2; ntp++) {
                uint32_t addr = bSt + (bRowBase + ntp * 16) * 64 +
                                (((ks * 2 + (q & 1)) ^ pb) * 16);
                LDSM4(b[2*ntp][0], b[2*ntp][1], b[2*ntp+1][0], b[2*ntp+1][1], addr);
            }
            #pragma unroll
            for (int mt = 0; mt < 4; mt++)
                #pragma unroll
                for (int nt = 0; nt < 4; nt++)
                    mma_bf16(acc[mt][nt], a[mt][0], a[mt][1], a[mt][2], a[mt][3],
                             b[nt][0], b[nt][1]);
        }
    };

    const int nS = K / BKq;
    ldg(0, 0);
    ldg(1, BKq);
    for (int it = 0; it < nS; it++) {
        CP_WAIT1();
        __syncthreads();
        if (it + 2 < nS) ldg((it + 2) % 3, (it + 2) * BKq);
        compute(it % 3);
    }

    const int g = lane >> 2, tig = lane & 3;
    #pragma unroll
    for (int mt = 0; mt < 4; mt++) {
        long r0 = m0g + wm + mt * 16 + g;
        long r1 = r0 + 8;
        #pragma unroll
        for (int nt = 0; nt < 4; nt++) {
            long c = n0g + wn + nt * 8 + 2 * tig;
            float v0 = acc[mt][nt][0] * scale;
            float v1 = acc[mt][nt][1] * scale;
            float v2 = acc[mt][nt][2] * scale;
            float v3 = acc[mt][nt][3] * scale;
            if (bias) {
                float b0 = bias[c], b1 = bias[c + 1];
                v0 += b0; v1 += b1; v2 += b0; v3 += b1;
            }
            if (res) {
                v0 += res[r0 * ldr + c];
                v1 += res[r0 * ldr + c + 1];
                v2 += res[r1 * ldr + c];
                v3 += res[r1 * ldr + c + 1];
            }
            if (C) {
                *(float2*)(C + r0 * ldc + c) = make_float2(v0, v1);
                *(float2*)(C + r1 * ldc + c) = make_float2(v2, v3);
            }
            if (Cb) {
                *(uint32_t*)(Cb + r0 * ldc + c) = pack_bf16(v0, v1);
                *(uint32_t*)(Cb + r1 * ldc + c) = pack_bf16(v2, v3);
            }
        }
    }
}

// ================= fused flash attention (deferred row-sum reduction) ========
#define FA_SMEM (32768 + 4 * 16384 + 8192)
#define NCHUNK (S / 64)

__global__ __launch_bounds__(256, 2) void flash_attn(
    const bf16* __restrict__ Qg, const bf16* __restrict__ Kg,
    const bf16* __restrict__ Vg, const float* __restrict__ tbg,
    bf16* __restrict__ ctx)
{
    extern __shared__ __align__(128) unsigned char fsm[];
    const uint32_t sb = (uint32_t)__cvta_generic_to_shared(fsm);
    const uint32_t qB  = sb;
    const uint32_t tbB = sb + 98304;
    float* tbS = (float*)(fsm + 98304);

    const int tid = threadIdx.x;
    const int w = tid >> 5, lane = tid & 31;
    const int q = lane >> 3, r = lane & 7;
    const int g = lane >> 2, tig = lane & 3;
    const int m0 = blockIdx.x * 128;
    const int h  = blockIdx.y;

    const bf16* Qp = Qg + h * D;
    const bf16* Kp = Kg + h * D;
    const bf16* Vp = Vg + h * D;
    const float* tbh = tbg + h * S;

    // ---- load Q tile + tb row (grouped with chunk 0) ----
    {
        int row = tid >> 1, half = tid & 1;
        const bf16* src = Qp + (long)(m0 + row) * E + half * 64;
        uint32_t dst = qB + row * 256;
        #pragma unroll
        for (int c = 0; c < 8; c++) {
            int ch = half * 8 + c;
            cp16(dst + ((ch ^ (row & 7)) * 16), src + c * 8);
        }
        cp16(tbB + tid * 32,      tbh + tid * 8);
        cp16(tbB + tid * 32 + 16, tbh + tid * 8 + 4);
    }

    auto ldkv = [&](int buf, int j) {
        uint32_t base = sb + 32768 + buf * 32768;
        const int half = tid & 1;
        int row  = (tid & 127) >> 1;
        const bf16* src = (tid < 128)
            ? (Kp + (long)(j * 64 + row) * E + half * 64)
            : (Vp + (long)(j * 64 + row) * E + half * 64);
        uint32_t dst = base + (tid < 128 ? 0 : 16384) + row * 256;
        #pragma unroll
        for (int c = 0; c < 8; c++) {
            int ch = half * 8 + c;
            cp16(dst + ((ch ^ (row & 7)) * 16), src + c * 8);
        }
    };

    ldkv(0, 0);
    CP_COMMIT();

    float o[16][4];
    #pragma unroll
    for (int i = 0; i < 16; i++)
        #pragma unroll
        for (int t = 0; t < 4; t++) o[i][t] = 0.0f;
    float rmax0 = -INFINITY, rmax1 = -INFINITY;
    float rsum0 = 0.0f, rsum1 = 0.0f;   // per-thread partials (reduced at end)

    const int aRow = w * 16 + ((q & 1) << 3) + r;

    for (int j = 0; j < NCHUNK; j++) {
        const int b = j & 1;
        CP_WAIT0();
        __syncthreads();
        if (j + 1 < NCHUNK) { ldkv(b ^ 1, j + 1); CP_COMMIT(); }

        const uint32_t kBuf = sb + 32768 + b * 32768;
        const uint32_t vBuf = kBuf + 16384;

        // ---- scores: S = Q K^T ----
        float sc[8][4];
        #pragma unroll
        for (int nf = 0; nf < 8; nf++)
            #pragma unroll
            for (int t = 0; t < 4; t++) sc[nf][t] = 0.0f;

        #pragma unroll
        for (int kc = 0; kc < 8; kc++) {
            uint32_t a0, a1, a2, a3;
            LDSM4(a0, a1, a2, a3,
                  qB + aRow * 256 + (((2 * kc + (q >> 1)) ^ r) * 16));
            #pragma unroll
            for (int ntg = 0; ntg < 4; ntg++) {
                uint32_t b0, b1, b2, b3;
                int nRow = ntg * 16 + ((q >> 1) << 3) + r;
                LDSM4(b0, b1, b2, b3,
                      kBuf + nRow * 256 + (((2 * kc + (q & 1)) ^ r) * 16));
                mma_bf16(sc[2 * ntg],     a0, a1, a2, a3, b0, b1);
                mma_bf16(sc[2 * ntg + 1], a0, a1, a2, a3, b2, b3);
            }
        }

        // ---- scale (base-2) + time bias + online softmax ----
        float mxn0 = rmax0, mxn1 = rmax1;
        #pragma unroll
        for (int nf = 0; nf < 8; nf++) {
            int col = j * 64 + nf * 8 + 2 * tig;
            float t0 = tbS[col], t1 = tbS[col + 1];   // pre-scaled by log2e
            sc[nf][0] = fmaf(sc[nf][0], SCALE2, t0);
            sc[nf][1] = fmaf(sc[nf][1], SCALE2, t1);
            sc[nf][2] = fmaf(sc[nf][2], SCALE2, t0);
            sc[nf][3] = fmaf(sc[nf][3], SCALE2, t1);
            mxn0 = fmaxf(mxn0, fmaxf(sc[nf][0], sc[nf][1]));
            mxn1 = fmaxf(mxn1, fmaxf(sc[nf][2], sc[nf][3]));
        }
        mxn0 = fmaxf(mxn0, __shfl_xor_sync(0xffffffffu, mxn0, 1));
        mxn0 = fmaxf(mxn0, __shfl_xor_sync(0xffffffffu, mxn0, 2));
        mxn1 = fmaxf(mxn1, __shfl_xor_sync(0xffffffffu, mxn1, 1));
        mxn1 = fmaxf(mxn1, __shfl_xor_sync(0xffffffffu, mxn1, 2));

        float f0 = ex2(rmax0 - mxn0);
        float f1 = ex2(rmax1 - mxn1);
        rmax0 = mxn0; rmax1 = mxn1;

        // per-thread local sums only — NO cross-lane reduction here
        float ls0 = 0.0f, ls1 = 0.0f;
        #pragma unroll
        for (int nf = 0; nf < 8; nf++) {
            sc[nf][0] = ex2(sc[nf][0] - mxn0);
            sc[nf][1] = ex2(sc[nf][1] - mxn0);
            sc[nf][2] = ex2(sc[nf][2] - mxn1);
            sc[nf][3] = ex2(sc[nf][3] - mxn1);
            ls0 += sc[nf][0] + sc[nf][1];
            ls1 += sc[nf][2] + sc[nf][3];
        }
        rsum0 = rsum0 * f0 + ls0;   // mxn is quad-uniform -> partials consistent
        rsum1 = rsum1 * f1 + ls1;

        #pragma unroll
        for (int nf2 = 0; nf2 < 16; nf2++) {
            o[nf2][0] *= f0; o[nf2][1] *= f0;
            o[nf2][2] *= f1; o[nf2][3] *= f1;
        }

        uint32_t pA[4][4];
        #pragma unroll
        for (int kc2 = 0; kc2 < 4; kc2++) {
            pA[kc2][0] = pack_bf16(sc[2 * kc2][0],     sc[2 * kc2][1]);
            pA[kc2][1] = pack_bf16(sc[2 * kc2][2],     sc[2 * kc2][3]);
            pA[kc2][2] = pack_bf16(sc[2 * kc2 + 1][0], sc[2 * kc2 + 1][1]);
            pA[kc2][3] = pack_bf16(sc[2 * kc2 + 1][2], sc[2 * kc2 + 1][3]);
        }

        // ---- O += P V ----
        #pragma unroll
        for (int kc2 = 0; kc2 < 4; kc2++) {
            int kRow = kc2 * 16 + ((q & 1) << 3) + r;
            #pragma unroll
            for (int ntg = 0; ntg < 8; ntg++) {
                uint32_t b0, b1, b2, b3;
                LDSM4T(b0, b1, b2, b3,
                       vBuf + kRow * 256 + ((((ntg << 1) + (q >> 1)) ^ r) * 16));
                mma_bf16(o[2 * ntg],     pA[kc2][0], pA[kc2][1], pA[kc2][2], pA[kc2][3], b0, b1);
                mma_bf16(o[2 * ntg + 1], pA[kc2][0], pA[kc2][1], pA[kc2][2], pA[kc2][3], b2, b3);
            }
        }
    }

    // ---- epilogue: quad-reduce deferred row sums, then normalize ----
    rsum0 += __shfl_xor_sync(0xffffffffu, rsum0, 1);
    rsum0 += __shfl_xor_sync(0xffffffffu, rsum0, 2);
    rsum1 += __shfl_xor_sync(0xffffffffu, rsum1, 1);
    rsum1 += __shfl_xor_sync(0xffffffffu, rsum1, 2);
    float i0 = 1.0f / rsum0, i1 = 1.0f / rsum1;
    long r0 = m0 + w * 16 + g;
    long r1 = r0 + 8;
    bf16* c0 = ctx + r0 * E + h * D;
    bf16* c1 = ctx + r1 * E + h * D;
    #pragma unroll
    for (int nf2 = 0; nf2 < 16; nf2++) {
        int col = nf2 * 8 + 2 * tig;
        *(uint32_t*)(c0 + col) = pack_bf16(o[nf2][0] * i0, o[nf2][1] * i0);
        *(uint32_t*)(c1 + col) = pack_bf16(o[nf2][2] * i1, o[nf2][3] * i1);
    }
}

// ---------------- time bias (writes tb * log2e) ------------------------------
__global__ __launch_bounds__(512) void time_bias_kernel(
    const float* __restrict__ te, const float* __restrict__ tpw,
    const float* __restrict__ tpb, float* __restrict__ tb)
{
    int s = blockIdx.x;
    int w = threadIdx.x >> 5, lane = threadIdx.x & 31;
    const float4* rr   = (const float4*)(te  + (long)s * E);
    const float4* wrow = (const float4*)(tpw + (long)w * E);
    float acc = 0.0f;
    for (int e = lane; e < E / 4; e += 32) {
        float4 a = rr[e], b = wrow[e];
        acc += a.x * b.x + a.y * b.y + a.z * b.z + a.w * b.w;
    }
    acc = warpReduceSum(acc);
    if (lane == 0) tb[w * S + s] = (acc + tpb[w]) * LOG2E;
}

// ---------------- LayerNorm --------------------------------------------------
__global__ __launch_bounds__(256) void layernorm_kernel(
    const float* __restrict__ x, const float* __restrict__ g,
    const float* __restrict__ b, float* __restrict__ out)
{
    const float* xr = x + (long)blockIdx.x * E;
    float*       yr = out + (long)blockIdx.x * E;
    int tid = threadIdx.x;
    float vals[8];
    float s = 0.0f, s2 = 0.0f;
    #pragma unroll
    for (int i = 0; i < 8; i++) {
        float v = xr[tid + i * 256];
        vals[i] = v;
        s += v;
        s2 += v * v;
    }
    s  = blockReduce256<false>(s);
    s2 = blockReduce256<false>(s2);
    float mean = s * (1.0f / E);
    float var  = s2 * (1.0f / E) - mean * mean;
    float rstd = rsqrtf(var + 1e-5f);
    #pragma unroll
    for (int i = 0; i < 8; i++) {
        int c = tid + i * 256;
        yr[c] = (vals[i] - mean) * rstd * g[c] + b[c];
    }
}

// ---------------- launch -----------------------------------------------------
extern "C" void kernel_launch(void* const* d_in, const int* in_sizes, int n_in,
                              void* d_out, int out_size)
{
    const float* query    = (const float*)d_in[0];
    const float* key      = (const float*)d_in[1];
    const float* value    = (const float*)d_in[2];
    const float* time_emb = (const float*)d_in[3];
    const float* in_w     = (const float*)d_in[4];
    const float* in_b     = (const float*)d_in[5];
    const float* out_w    = (const float*)d_in[6];
    const float* out_b    = (const float*)d_in[7];
    const float* tp_w     = (const float*)d_in[8];
    const float* tp_b     = (const float*)d_in[9];
    const float* ln_g     = (const float*)d_in[10];
    const float* ln_b     = (const float*)d_in[11];

    bf16 *in3, *wb, *owb, *QKV, *ctxb;
    float *tb, *x;
    cudaGetSymbolAddress((void**)&in3,  g_in3);
    cudaGetSymbolAddress((void**)&wb,   g_wb);
    cudaGetSymbolAddress((void**)&owb,  g_owb);
    cudaGetSymbolAddress((void**)&QKV,  g_QKV);
    cudaGetSymbolAddress((void**)&ctxb, g_ctxb);
    cudaGetSymbolAddress((void**)&tb,   g_tb);
    cudaGetSymbolAddress((void**)&x,    g_x);

    cudaFuncSetAttribute(flash_attn, cudaFuncAttributeMaxDynamicSharedMemorySize, FA_SMEM);

    // 0. one-time fp32 -> bf16 conversions: single exact-sized launch
    const int n4a = (L * E) / 4;
    const int n4w = (3 * E * E) / 4;
    const int n4o = (E * E) / 4;
    CvtJobs jobs;
    jobs.in[0] = (const float4*)query;  jobs.out[0] = (uint2*)in3;                  jobs.n4[0] = n4a;
    jobs.in[1] = (const float4*)key;    jobs.out[1] = (uint2*)(in3 + (long)L * E);  jobs.n4[1] = n4a;
    jobs.in[2] = (const float4*)value;  jobs.out[2] = (uint2*)(in3 + 2L * L * E);   jobs.n4[2] = n4a;
    jobs.in[3] = (const float4*)in_w;   jobs.out[3] = (uint2*)wb;                   jobs.n4[3] = n4w;
    jobs.in[4] = (const float4*)out_w;  jobs.out[4] = (uint2*)owb;                  jobs.n4[4] = n4o;
    jobs.off[0] = 0;
    jobs.off[1] = jobs.off[0] + (n4a + 1023) / 1024;
    jobs.off[2] = jobs.off[1] + (n4a + 1023) / 1024;
    jobs.off[3] = jobs.off[2] + (n4a + 1023) / 1024;
    jobs.off[4] = jobs.off[3] + (n4w + 1023) / 1024;
    jobs.off[5] = jobs.off[4] + (n4o + 1023) / 1024;
    cvt_multi<<<jobs.off[5], 256>>>(jobs);

    // 1. time bias (H x S), pre-scaled by log2e
    time_bias_kernel<<<S, 512>>>(time_emb, tp_w, tp_b, tb);

    // 2. Q,K,V projections in one launch (grid.z selects q/k/v)
    bf16* Qb = QKV;
    bf16* Kb = QKV + (long)L * E;
    bf16* Vb = QKV + 2L * L * E;
    dim3 gqkv(E / BN, L / BM, 3);
    bgemm_nt<<<gqkv, 256>>>(in3, wb, nullptr, QKV,
                            E, E, E, E,
                            (long)L * E, (long)E * E, (long)L * E,
                            in_b, (long)E, nullptr, 0, 1.0f);

    // 3-5. fused attention (scores + time bias + softmax + PV)
    dim3 gfa(L / 128, H);
    flash_attn<<<gfa, 256, FA_SMEM>>>(Qb, Kb, Vb, tb, ctxb);

    // 6. out projection + residual (fp32 out)
    dim3 gop(E / BN, L / BM, 1);
    bgemm_nt<<<gop, 256>>>(ctxb, owb, x, nullptr,
                           E, E, E, E, 0, 0, 0,
                           out_b, 0, query, E, 1.0f);

    // 7. LayerNorm -> d_out
    layernorm_kernel<<<L, 256>>>(x, ln_g, ln_b, (float*)d_out);
}

// round 14
// speedup vs baseline: 1.0025x; 1.0025x over previous
#include <cuda_runtime.h>
#include <cuda_bf16.h>
#include <math.h>
#include <stdint.h>

// Problem constants
#define L 2048
#define S 2048
#define E 2048
#define H 16
#define D 128
#define SCALE 0.08838834764831843f      // 1/sqrt(128)
#define LOG2E 1.4426950408889634f
#define SCALE2 (SCALE * LOG2E)          // scale in base-2 domain

typedef __nv_bfloat16 bf16;

// ---------------- scratch (static device globals; no allocation) -------------
__device__ bf16  g_in3[3L * L * E];          // q,k,v inputs (bf16), stacked
__device__ bf16  g_wb[3L * E * E];           // in_proj weights bf16
__device__ bf16  g_owb[(long)E * E];         // out_proj weights bf16
__device__ bf16  g_QKV[3L * L * E];          // Q | K | V (each [L,E])
__device__ bf16  g_ctxb[(long)L * E];
__device__ float g_tb[H * S];                // time bias PRE-SCALED by log2(e)
__device__ float g_x[(long)L * E];

// ---------------- ptx helpers ------------------------------------------------
__device__ __forceinline__ uint32_t pack_bf16(float x, float y) {
    uint32_t u;
    asm("cvt.rn.bf16x2.f32 %0, %1, %2;" : "=r"(u) : "f"(y), "f"(x));
    return u;
}

__device__ __forceinline__ float ex2(float x) {
    float r;
    asm("ex2.approx.f32 %0, %1;" : "=f"(r) : "f"(x));
    return r;
}

__device__ __forceinline__ void mma_bf16(float c[4],
                                         uint32_t a0, uint32_t a1, uint32_t a2, uint32_t a3,
                                         uint32_t b0, uint32_t b1) {
    asm volatile(
        "mma.sync.aligned.m16n8k16.row.col.f32.bf16.bf16.f32 "
        "{%0,%1,%2,%3}, {%4,%5,%6,%7}, {%8,%9}, {%0,%1,%2,%3};\n"
        : "+f"(c[0]), "+f"(c[1]), "+f"(c[2]), "+f"(c[3])
        : "r"(a0), "r"(a1), "r"(a2), "r"(a3), "r"(b0), "r"(b1));
}

__device__ __forceinline__ void cp16(uint32_t dst, const void* src) {
    asm volatile("cp.async.cg.shared.global [%0], [%1], 16;" :: "r"(dst), "l"(src));
}
#define CP_COMMIT() asm volatile("cp.async.commit_group;")
#define CP_WAIT1()  asm volatile("cp.async.wait_group 1;")
#define CP_WAIT0()  asm volatile("cp.async.wait_group 0;")

#define LDSM4(r0, r1, r2, r3, addr)                                            \
    asm volatile("ldmatrix.sync.aligned.m8n8.x4.shared.b16 {%0,%1,%2,%3}, [%4];" \
                 : "=r"(r0), "=r"(r1), "=r"(r2), "=r"(r3) : "r"(addr))
#define LDSM4T(r0, r1, r2, r3, addr)                                           \
    asm volatile("ldmatrix.sync.aligned.m8n8.x4.trans.shared.b16 {%0,%1,%2,%3}, [%4];" \
                 : "=r"(r0), "=r"(r1), "=r"(r2), "=r"(r3) : "r"(addr))

__device__ __forceinline__ float warpReduceSum(float v) {
    #pragma unroll
    for (int o = 16; o > 0; o >>= 1) v += __shfl_xor_sync(0xffffffffu, v, o);
    return v;
}
template<bool MAX>
__device__ __forceinline__ float blockReduce256(float v) {
    __shared__ float sh[8];
    int lane = threadIdx.x & 31, wid = threadIdx.x >> 5;
    #pragma unroll
    for (int o = 16; o > 0; o >>= 1)
        v = MAX ? fmaxf(v, __shfl_xor_sync(0xffffffffu, v, o))
                : v + __shfl_xor_sync(0xffffffffu, v, o);
    if (lane == 0) sh[wid] = v;
    __syncthreads();
    if (wid == 0) {
        float t = (lane < 8) ? sh[lane] : (MAX ? -INFINITY : 0.0f);
        #pragma unroll
        for (int o = 4; o > 0; o >>= 1)
            t = MAX ? fmaxf(t, __shfl_xor_sync(0xffffffffu, t, o))
                    : t + __shfl_xor_sync(0xffffffffu, t, o);
        if (lane == 0) sh[0] = t;
    }
    __syncthreads();
    float r = sh[0];
    __syncthreads();
    return r;
}

// ---------------- batched fp32 -> bf16 conversion (exact-sized 1D grid) ------
struct CvtJobs {
    const float4* in[5];
    uint2*        out[5];
    int           n4[5];
    int           off[6];   // block offsets, off[5] = total blocks
};

__global__ __launch_bounds__(256) void cvt_multi(CvtJobs jobs)
{
    int b = blockIdx.x;
    int z = 0;
    #pragma unroll
    for (int k = 1; k < 5; k++) z += (b >= jobs.off[k]);
    const float4* __restrict__ in = jobs.in[z];
    uint2* __restrict__ out = jobs.out[z];
    const int n4 = jobs.n4[z];
    int i0 = (b - jobs.off[z]) * 1024 + threadIdx.x;
    float4 v[4];
    #pragma unroll
    for (int j = 0; j < 4; j++) {
        int i = i0 + j * 256;
        if (i < n4) v[j] = in[i];
    }
    #pragma unroll
    for (int j = 0; j < 4; j++) {
        int i = i0 + j * 256;
        if (i < n4)
            out[i] = make_uint2(pack_bf16(v[j].x, v[j].y), pack_bf16(v[j].z, v[j].w));
    }
}

// ================= mma.sync NT GEMM (R6/R8 proven config) ====================
#define BM 128
#define BN 128
#define BKq 32
#define STAGE_BYTES 16384

__global__ __launch_bounds__(256, 2) void bgemm_nt(
    const bf16* __restrict__ A, const bf16* __restrict__ B,
    float* __restrict__ C, bf16* __restrict__ Cb,
    int K, int lda, int ldb, int ldc,
    long aZ, long bZ, long cZ,
    const float* __restrict__ bias, long biasZ,
    const float* __restrict__ res, int ldr,
    float scale)
{
    const int z = blockIdx.z;
    A += (long)z * aZ;
    B += (long)z * bZ;
    if (C)  C  += (long)z * cZ;
    if (Cb) Cb += (long)z * cZ;
    if (bias) bias += (long)z * biasZ;

    __shared__ __align__(16) unsigned char sm[3 * STAGE_BYTES];
    const uint32_t smBase = (uint32_t)__cvta_generic_to_shared(sm);

    const int tid  = threadIdx.x;
    const int wid  = tid >> 5;
    const int lane = tid & 31;
    const int wm = (wid & 1) * 64;
    const int wn = (wid >> 1) * 32;

    const long m0g = (long)blockIdx.y * BM;
    const long n0g = (long)blockIdx.x * BN;

    const int rowA = tid >> 2;
    const int cA   = tid & 3;
    const uint32_t aOff = rowA * 64 + ((cA ^ ((rowA >> 1) & 3)) * 16);
    const bf16* gA0 = A + (m0g + rowA) * (long)lda + cA * 8;
    const bf16* gA1 = gA0 + 64 * (long)lda;
    const bf16* gB0 = B + (n0g + rowA) * (long)ldb + cA * 8;
    const bf16* gB1 = gB0 + 64 * (long)ldb;

    auto ldg = [&](int st, int k0) {
        uint32_t aSt = smBase + st * STAGE_BYTES;
        uint32_t bSt = aSt + 8192;
        cp16(aSt + aOff,        gA0 + k0);
        cp16(aSt + aOff + 4096, gA1 + k0);
        cp16(bSt + aOff,        gB0 + k0);
        cp16(bSt + aOff + 4096, gB1 + k0);
        CP_COMMIT();
    };

    const int q = lane >> 3, r = lane & 7;
    const int aRowBase = wm + ((q & 1) << 3) + r;
    const int pa = (aRowBase >> 1) & 3;
    const int bRowBase = wn + ((q >> 1) << 3) + r;
    const int pb = (bRowBase >> 1) & 3;

    float acc[4][4][4];
    #pragma unroll
    for (int i = 0; i < 4; i++)
        #pragma unroll
        for (int j = 0; j < 4; j++)
            #pragma unroll
            for (int t = 0; t < 4; t++) acc[i][j][t] = 0.0f;

    auto compute = [&](int st) {
        uint32_t aSt = smBase + st * STAGE_BYTES;
        uint32_t bSt = aSt + 8192;
        #pragma unroll
        for (int ks = 0; ks < 2; ks++) {
            uint32_t a[4][4];
            #pragma unroll
            for (int mt = 0; mt < 4; mt++) {
                uint32_t addr = aSt + (aRowBase + mt * 16) * 64 +
                                (((ks * 2 + (q >> 1)) ^ pa) * 16);
                LDSM4(a[mt][0], a[mt][1], a[mt][2], a[mt][3], addr);
            }
            uint32_t b[4][2];
            #pragma unroll
            for (int ntp = 0; ntp < 2; ntp++) {
                uint32_t addr = bSt + (bRowBase + ntp * 16) * 64 +
                                (((ks * 2 + (q & 1)) ^ pb) * 16);
                LDSM4(b[2*ntp][0], b[2*ntp][1], b[2*ntp+1][0], b[2*ntp+1][1], addr);
            }
            #pragma unroll
            for (int mt = 0; mt < 4; mt++)
                #pragma unroll
                for (int nt = 0; nt < 4; nt++)
                    mma_bf16(acc[mt][nt], a[mt][0], a[mt][1], a[mt][2], a[mt][3],
                             b[nt][0], b[nt][1]);
        }
    };

    const int nS = K / BKq;
    ldg(0, 0);
    ldg(1, BKq);
    for (int it = 0; it < nS; it++) {
        CP_WAIT1();
        __syncthreads();
        if (it + 2 < nS) ldg((it + 2) % 3, (it + 2) * BKq);
        compute(it % 3);
    }

    const int g = lane >> 2, tig = lane & 3;
    #pragma unroll
    for (int mt = 0; mt < 4; mt++) {
        long r0 = m0g + wm + mt * 16 + g;
        long r1 = r0 + 8;
        #pragma unroll
        for (int nt = 0; nt < 4; nt++) {
            long c = n0g + wn + nt * 8 + 2 * tig;
            float v0 = acc[mt][nt][0] * scale;
            float v1 = acc[mt][nt][1] * scale;
            float v2 = acc[mt][nt][2] * scale;
            float v3 = acc[mt][nt][3] * scale;
            if (bias) {
                float b0 = bias[c], b1 = bias[c + 1];
                v0 += b0; v1 += b1; v2 += b0; v3 += b1;
            }
            if (res) {
                v0 += res[r0 * ldr + c];
                v1 += res[r0 * ldr + c + 1];
                v2 += res[r1 * ldr + c];
                v3 += res[r1 * ldr + c + 1];
            }
            if (C) {
                *(float2*)(C + r0 * ldc + c) = make_float2(v0, v1);
                *(float2*)(C + r1 * ldc + c) = make_float2(v2, v3);
            }
            if (Cb) {
                *(uint32_t*)(Cb + r0 * ldc + c) = pack_bf16(v0, v1);
                *(uint32_t*)(Cb + r1 * ldc + c) = pack_bf16(v2, v3);
            }
        }
    }
}

// ================= fused flash attention (best-known: R13 + micro-trims) =====
#define FA_SMEM (32768 + 4 * 16384 + 8192)
#define NCHUNK (S / 64)

__global__ __launch_bounds__(256, 2) void flash_attn(
    const bf16* __restrict__ Qg, const bf16* __restrict__ Kg,
    const bf16* __restrict__ Vg, const float* __restrict__ tbg,
    bf16* __restrict__ ctx)
{
    extern __shared__ __align__(128) unsigned char fsm[];
    const uint32_t sb = (uint32_t)__cvta_generic_to_shared(fsm);
    const uint32_t qB  = sb;
    const uint32_t tbB = sb + 98304;
    const float2* tbS2 = (const float2*)(fsm + 98304);

    const int tid = threadIdx.x;
    const int w = tid >> 5, lane = tid & 31;
    const int q = lane >> 3, r = lane & 7;
    const int g = lane >> 2, tig = lane & 3;
    const int m0 = blockIdx.x * 128;
    const int h  = blockIdx.y;

    const bf16* Qp = Qg + h * D;
    const bf16* Kp = Kg + h * D;
    const bf16* Vp = Vg + h * D;
    const float* tbh = tbg + h * S;

    // ---- load Q tile + tb row (grouped with chunk 0) ----
    {
        int row = tid >> 1, half = tid & 1;
        const bf16* src = Qp + (long)(m0 + row) * E + half * 64;
        uint32_t dst = qB + row * 256;
        #pragma unroll
        for (int c = 0; c < 8; c++) {
            int ch = half * 8 + c;
            cp16(dst + ((ch ^ (row & 7)) * 16), src + c * 8);
        }
        cp16(tbB + tid * 32,      tbh + tid * 8);
        cp16(tbB + tid * 32 + 16, tbh + tid * 8 + 4);
    }

    auto ldkv = [&](int buf, int j) {
        uint32_t base = sb + 32768 + buf * 32768;
        const int half = tid & 1;
        int row  = (tid & 127) >> 1;
        const bf16* src = (tid < 128)
            ? (Kp + (long)(j * 64 + row) * E + half * 64)
            : (Vp + (long)(j * 64 + row) * E + half * 64);
        uint32_t dst = base + (tid < 128 ? 0 : 16384) + row * 256;
        #pragma unroll
        for (int c = 0; c < 8; c++) {
            int ch = half * 8 + c;
            cp16(dst + ((ch ^ (row & 7)) * 16), src + c * 8);
        }
    };

    ldkv(0, 0);
    CP_COMMIT();

    float o[16][4];
    #pragma unroll
    for (int i = 0; i < 16; i++)
        #pragma unroll
        for (int t = 0; t < 4; t++) o[i][t] = 0.0f;
    float rmax0 = -INFINITY, rmax1 = -INFINITY;
    float rsum0 = 0.0f, rsum1 = 0.0f;   // per-thread partials (reduced at end)

    const int aRow = w * 16 + ((q & 1) << 3) + r;

    for (int j = 0; j < NCHUNK; j++) {
        const int b = j & 1;
        CP_WAIT0();
        __syncthreads();
        if (j + 1 < NCHUNK) { ldkv(b ^ 1, j + 1); CP_COMMIT(); }

        const uint32_t kBuf = sb + 32768 + b * 32768;
        const uint32_t vBuf = kBuf + 16384;

        // ---- scores: S = Q K^T ----
        float sc[8][4];
        #pragma unroll
        for (int nf = 0; nf < 8; nf++)
            #pragma unroll
            for (int t = 0; t < 4; t++) sc[nf][t] = 0.0f;

        #pragma unroll
        for (int kc = 0; kc < 8; kc++) {
            uint32_t a0, a1, a2, a3;
            LDSM4(a0, a1, a2, a3,
                  qB + aRow * 256 + (((2 * kc + (q >> 1)) ^ r) * 16));
            #pragma unroll
            for (int ntg = 0; ntg < 4; ntg++) {
                uint32_t b0, b1, b2, b3;
                int nRow = ntg * 16 + ((q >> 1) << 3) + r;
                LDSM4(b0, b1, b2, b3,
                      kBuf + nRow * 256 + (((2 * kc + (q & 1)) ^ r) * 16));
                mma_bf16(sc[2 * ntg],     a0, a1, a2, a3, b0, b1);
                mma_bf16(sc[2 * ntg + 1], a0, a1, a2, a3, b2, b3);
            }
        }

        // ---- scale (base-2) + time bias + online softmax ----
        float mxn0 = rmax0, mxn1 = rmax1;
        #pragma unroll
        for (int nf = 0; nf < 8; nf++) {
            float2 t = tbS2[(j * 64 + nf * 8) / 2 + tig];   // LDS.64, pre-scaled
            sc[nf][0] = fmaf(sc[nf][0], SCALE2, t.x);
            sc[nf][1] = fmaf(sc[nf][1], SCALE2, t.y);
            sc[nf][2] = fmaf(sc[nf][2], SCALE2, t.x);
            sc[nf][3] = fmaf(sc[nf][3], SCALE2, t.y);
            mxn0 = fmaxf(mxn0, fmaxf(sc[nf][0], sc[nf][1]));
            mxn1 = fmaxf(mxn1, fmaxf(sc[nf][2], sc[nf][3]));
        }
        mxn0 = fmaxf(mxn0, __shfl_xor_sync(0xffffffffu, mxn0, 1));
        mxn0 = fmaxf(mxn0, __shfl_xor_sync(0xffffffffu, mxn0, 2));
        mxn1 = fmaxf(mxn1, __shfl_xor_sync(0xffffffffu, mxn1, 1));
        mxn1 = fmaxf(mxn1, __shfl_xor_sync(0xffffffffu, mxn1, 2));

        // issue the two dependent MUFUs first so their latency overlaps below
        float f0 = ex2(rmax0 - mxn0);
        float f1 = ex2(rmax1 - mxn1);
        rmax0 = mxn0; rmax1 = mxn1;

        // per-thread local sums only — NO cross-lane reduction here
        float ls0 = 0.0f, ls1 = 0.0f;
        #pragma unroll
        for (int nf = 0; nf < 8; nf++) {
            sc[nf][0] = ex2(sc[nf][0] - mxn0);
            sc[nf][1] = ex2(sc[nf][1] - mxn0);
            sc[nf][2] = ex2(sc[nf][2] - mxn1);
            sc[nf][3] = ex2(sc[nf][3] - mxn1);
            ls0 += sc[nf][0] + sc[nf][1];
            ls1 += sc[nf][2] + sc[nf][3];
        }
        rsum0 = rsum0 * f0 + ls0;   // mxn is quad-uniform -> partials consistent
        rsum1 = rsum1 * f1 + ls1;

        #pragma unroll
        for (int nf2 = 0; nf2 < 16; nf2++) {
            o[nf2][0] *= f0; o[nf2][1] *= f0;
            o[nf2][2] *= f1; o[nf2][3] *= f1;
        }

        uint32_t pA[4][4];
        #pragma unroll
        for (int kc2 = 0; kc2 < 4; kc2++) {
            pA[kc2][0] = pack_bf16(sc[2 * kc2][0],     sc[2 * kc2][1]);
            pA[kc2][1] = pack_bf16(sc[2 * kc2][2],     sc[2 * kc2][3]);
            pA[kc2][2] = pack_bf16(sc[2 * kc2 + 1][0], sc[2 * kc2 + 1][1]);
            pA[kc2][3] = pack_bf16(sc[2 * kc2 + 1][2], sc[2 * kc2 + 1][3]);
        }

        // ---- O += P V ----
        #pragma unroll
        for (int kc2 = 0; kc2 < 4; kc2++) {
            int kRow = kc2 * 16 + ((q & 1) << 3) + r;
            #pragma unroll
            for (int ntg = 0; ntg < 8; ntg++) {
                uint32_t b0, b1, b2, b3;
                LDSM4T(b0, b1, b2, b3,
                       vBuf + kRow * 256 + ((((ntg << 1) + (q >> 1)) ^ r) * 16));
                mma_bf16(o[2 * ntg],     pA[kc2][0], pA[kc2][1], pA[kc2][2], pA[kc2][3], b0, b1);
                mma_bf16(o[2 * ntg + 1], pA[kc2][0], pA[kc2][1], pA[kc2][2], pA[kc2][3], b2, b3);
            }
        }
    }

    // ---- epilogue: quad-reduce deferred row sums, then normalize ----
    rsum0 += __shfl_xor_sync(0xffffffffu, rsum0, 1);
    rsum0 += __shfl_xor_sync(0xffffffffu, rsum0, 2);
    rsum1 += __shfl_xor_sync(0xffffffffu, rsum1, 1);
    rsum1 += __shfl_xor_sync(0xffffffffu, rsum1, 2);
    float i0 = 1.0f / rsum0, i1 = 1.0f / rsum1;
    long r0 = m0 + w * 16 + g;
    long r1 = r0 + 8;
    bf16* c0 = ctx + r0 * E + h * D;
    bf16* c1 = ctx + r1 * E + h * D;
    #pragma unroll
    for (int nf2 = 0; nf2 < 16; nf2++) {
        int col = nf2 * 8 + 2 * tig;
        *(uint32_t*)(c0 + col) = pack_bf16(o[nf2][0] * i0, o[nf2][1] * i0);
        *(uint32_t*)(c1 + col) = pack_bf16(o[nf2][2] * i1, o[nf2][3] * i1);
    }
}

// ---------------- time bias (writes tb * log2e) ------------------------------
__global__ __launch_bounds__(512) void time_bias_kernel(
    const float* __restrict__ te, const float* __restrict__ tpw,
    const float* __restrict__ tpb, float* __restrict__ tb)
{
    int s = blockIdx.x;
    int w = threadIdx.x >> 5, lane = threadIdx.x & 31;
    const float4* rr   = (const float4*)(te  + (long)s * E);
    const float4* wrow = (const float4*)(tpw + (long)w * E);
    float acc = 0.0f;
    for (int e = lane; e < E / 4; e += 32) {
        float4 a = rr[e], b = wrow[e];
        acc += a.x * b.x + a.y * b.y + a.z * b.z + a.w * b.w;
    }
    acc = warpReduceSum(acc);
    if (lane == 0) tb[w * S + s] = (acc + tpb[w]) * LOG2E;
}

// ---------------- LayerNorm --------------------------------------------------
__global__ __launch_bounds__(256) void layernorm_kernel(
    const float* __restrict__ x, const float* __restrict__ g,
    const float* __restrict__ b, float* __restrict__ out)
{
    const float* xr = x + (long)blockIdx.x * E;
    float*       yr = out + (long)blockIdx.x * E;
    int tid = threadIdx.x;
    float vals[8];
    float s = 0.0f, s2 = 0.0f;
    #pragma unroll
    for (int i = 0; i < 8; i++) {
        float v = xr[tid + i * 256];
        vals[i] = v;
        s += v;
        s2 += v * v;
    }
    s  = blockReduce256<false>(s);
    s2 = blockReduce256<false>(s2);
    float mean = s * (1.0f / E);
    float var  = s2 * (1.0f / E) - mean * mean;
    float rstd = rsqrtf(var + 1e-5f);
    #pragma unroll
    for (int i = 0; i < 8; i++) {
        int c = tid + i * 256;
        yr[c] = (vals[i] - mean) * rstd * g[c] + b[c];
    }
}

// ---------------- launch -----------------------------------------------------
extern "C" void kernel_launch(void* const* d_in, const int* in_sizes, int n_in,
                              void* d_out, int out_size)
{
    const float* query    = (const float*)d_in[0];
    const float* key      = (const float*)d_in[1];
    const float* value    = (const float*)d_in[2];
    const float* time_emb = (const float*)d_in[3];
    const float* in_w     = (const float*)d_in[4];
    const float* in_b     = (const float*)d_in[5];
    const float* out_w    = (const float*)d_in[6];
    const float* out_b    = (const float*)d_in[7];
    const float* tp_w     = (const float*)d_in[8];
    const float* tp_b     = (const float*)d_in[9];
    const float* ln_g     = (const float*)d_in[10];
    const float* ln_b     = (const float*)d_in[11];

    bf16 *in3, *wb, *owb, *QKV, *ctxb;
    float *tb, *x;
    cudaGetSymbolAddress((void**)&in3,  g_in3);
    cudaGetSymbolAddress((void**)&wb,   g_wb);
    cudaGetSymbolAddress((void**)&owb,  g_owb);
    cudaGetSymbolAddress((void**)&QKV,  g_QKV);
    cudaGetSymbolAddress((void**)&ctxb, g_ctxb);
    cudaGetSymbolAddress((void**)&tb,   g_tb);
    cudaGetSymbolAddress((void**)&x,    g_x);

    cudaFuncSetAttribute(flash_attn, cudaFuncAttributeMaxDynamicSharedMemorySize, FA_SMEM);

    // 0. one-time fp32 -> bf16 conversions: single exact-sized launch
    const int n4a = (L * E) / 4;
    const int n4w = (3 * E * E) / 4;
    const int n4o = (E * E) / 4;
    CvtJobs jobs;
    jobs.in[0] = (const float4*)query;  jobs.out[0] = (uint2*)in3;                  jobs.n4[0] = n4a;
    jobs.in[1] = (const float4*)key;    jobs.out[1] = (uint2*)(in3 + (long)L * E);  jobs.n4[1] = n4a;
    jobs.in[2] = (const float4*)value;  jobs.out[2] = (uint2*)(in3 + 2L * L * E);   jobs.n4[2] = n4a;
    jobs.in[3] = (const float4*)in_w;   jobs.out[3] = (uint2*)wb;                   jobs.n4[3] = n4w;
    jobs.in[4] = (const float4*)out_w;  jobs.out[4] = (uint2*)owb;                  jobs.n4[4] = n4o;
    jobs.off[0] = 0;
    jobs.off[1] = jobs.off[0] + (n4a + 1023) / 1024;
    jobs.off[2] = jobs.off[1] + (n4a + 1023) / 1024;
    jobs.off[3] = jobs.off[2] + (n4a + 1023) / 1024;
    jobs.off[4] = jobs.off[3] + (n4w + 1023) / 1024;
    jobs.off[5] = jobs.off[4] + (n4o + 1023) / 1024;
    cvt_multi<<<jobs.off[5], 256>>>(jobs);

    // 1. time bias (H x S), pre-scaled by log2e
    time_bias_kernel<<<S, 512>>>(time_emb, tp_w, tp_b, tb);

    // 2. Q,K,V projections in one launch (grid.z selects q/k/v)
    bf16* Qb = QKV;
    bf16* Kb = QKV + (long)L * E;
    bf16* Vb = QKV + 2L * L * E;
    dim3 gqkv(E / BN, L / BM, 3);
    bgemm_nt<<<gqkv, 256>>>(in3, wb, nullptr, QKV,
                            E, E, E, E,
                            (long)L * E, (long)E * E, (long)L * E,
                            in_b, (long)E, nullptr, 0, 1.0f);

    // 3-5. fused attention (scores + time bias + softmax + PV)
    dim3 gfa(L / 128, H);
    flash_attn<<<gfa, 256, FA_SMEM>>>(Qb, Kb, Vb, tb, ctxb);

    // 6. out projection + residual (fp32 out)
    dim3 gop(E / BN, L / BM, 1);
    bgemm_nt<<<gop, 256>>>(ctxb, owb, x, nullptr,
                           E, E, E, E, 0, 0, 0,
                           out_b, 0, query, E, 1.0f);

    // 7. LayerNorm -> d_out
    layernorm_kernel<<<L, 256>>>(x, ln_g, ln_b, (float*)d_out);
}

// round 15
// speedup vs baseline: 1.0090x; 1.0065x over previous
#include <cuda_runtime.h>
#include <cuda_bf16.h>
#include <math.h>
#include <stdint.h>

// Problem constants
#define L 2048
#define S 2048
#define E 2048
#define H 16
#define D 128
#define SCALE 0.08838834764831843f      // 1/sqrt(128)
#define LOG2E 1.4426950408889634f
#define SCALE2 (SCALE * LOG2E)          // scale in base-2 domain

typedef __nv_bfloat16 bf16;

// ---------------- scratch (static device globals; no allocation) -------------
__device__ bf16  g_in3[3L * L * E];          // q,k,v inputs (bf16), stacked
__device__ bf16  g_wb[3L * E * E];           // in_proj weights bf16
__device__ bf16  g_owb[(long)E * E];         // out_proj weights bf16
__device__ bf16  g_QKV[3L * L * E];          // Q | K | V (each [L,E])
__device__ bf16  g_ctxb[(long)L * E];
__device__ float g_tb[H * S];                // time bias PRE-SCALED by log2(e)
__device__ float g_x[(long)L * E];

// ---------------- ptx helpers ------------------------------------------------
__device__ __forceinline__ uint32_t pack_bf16(float x, float y) {
    uint32_t u;
    asm("cvt.rn.bf16x2.f32 %0, %1, %2;" : "=r"(u) : "f"(y), "f"(x));
    return u;
}

__device__ __forceinline__ float ex2(float x) {
    float r;
    asm("ex2.approx.f32 %0, %1;" : "=f"(r) : "f"(x));
    return r;
}

__device__ __forceinline__ void mma_bf16(float c[4],
                                         uint32_t a0, uint32_t a1, uint32_t a2, uint32_t a3,
                                         uint32_t b0, uint32_t b1) {
    asm volatile(
        "mma.sync.aligned.m16n8k16.row.col.f32.bf16.bf16.f32 "
        "{%0,%1,%2,%3}, {%4,%5,%6,%7}, {%8,%9}, {%0,%1,%2,%3};\n"
        : "+f"(c[0]), "+f"(c[1]), "+f"(c[2]), "+f"(c[3])
        : "r"(a0), "r"(a1), "r"(a2), "r"(a3), "r"(b0), "r"(b1));
}

__device__ __forceinline__ void cp16(uint32_t dst, const void* src) {
    asm volatile("cp.async.cg.shared.global [%0], [%1], 16;" :: "r"(dst), "l"(src));
}
#define CP_COMMIT() asm volatile("cp.async.commit_group;")
#define CP_WAIT1()  asm volatile("cp.async.wait_group 1;")
#define CP_WAIT0()  asm volatile("cp.async.wait_group 0;")

#define LDSM4(r0, r1, r2, r3, addr)                                            \
    asm volatile("ldmatrix.sync.aligned.m8n8.x4.shared.b16 {%0,%1,%2,%3}, [%4];" \
                 : "=r"(r0), "=r"(r1), "=r"(r2), "=r"(r3) : "r"(addr))
#define LDSM4T(r0, r1, r2, r3, addr)                                           \
    asm volatile("ldmatrix.sync.aligned.m8n8.x4.trans.shared.b16 {%0,%1,%2,%3}, [%4];" \
                 : "=r"(r0), "=r"(r1), "=r"(r2), "=r"(r3) : "r"(addr))

__device__ __forceinline__ float warpReduceSum(float v) {
    #pragma unroll
    for (int o = 16; o > 0; o >>= 1) v += __shfl_xor_sync(0xffffffffu, v, o);
    return v;
}
template<bool MAX>
__device__ __forceinline__ float blockReduce256(float v) {
    __shared__ float sh[8];
    int lane = threadIdx.x & 31, wid = threadIdx.x >> 5;
    #pragma unroll
    for (int o = 16; o > 0; o >>= 1)
        v = MAX ? fmaxf(v, __shfl_xor_sync(0xffffffffu, v, o))
                : v + __shfl_xor_sync(0xffffffffu, v, o);
    if (lane == 0) sh[wid] = v;
    __syncthreads();
    if (wid == 0) {
        float t = (lane < 8) ? sh[lane] : (MAX ? -INFINITY : 0.0f);
        #pragma unroll
        for (int o = 4; o > 0; o >>= 1)
            t = MAX ? fmaxf(t, __shfl_xor_sync(0xffffffffu, t, o))
                    : t + __shfl_xor_sync(0xffffffffu, t, o);
        if (lane == 0) sh[0] = t;
    }
    __syncthreads();
    float r = sh[0];
    __syncthreads();
    return r;
}

// ---------------- batched fp32 -> bf16 conversion (exact-sized 1D grid) ------
struct CvtJobs {
    const float4* in[5];
    uint2*        out[5];
    int           n4[5];
    int           off[6];   // block offsets, off[5] = total blocks
};

__global__ __launch_bounds__(256) void cvt_multi(CvtJobs jobs)
{
    int b = blockIdx.x;
    int z = 0;
    #pragma unroll
    for (int k = 1; k < 5; k++) z += (b >= jobs.off[k]);
    const float4* __restrict__ in = jobs.in[z];
    uint2* __restrict__ out = jobs.out[z];
    const int n4 = jobs.n4[z];
    int i0 = (b - jobs.off[z]) * 1024 + threadIdx.x;
    float4 v[4];
    #pragma unroll
    for (int j = 0; j < 4; j++) {
        int i = i0 + j * 256;
        if (i < n4) v[j] = in[i];
    }
    #pragma unroll
    for (int j = 0; j < 4; j++) {
        int i = i0 + j * 256;
        if (i < n4)
            out[i] = make_uint2(pack_bf16(v[j].x, v[j].y), pack_bf16(v[j].z, v[j].w));
    }
}

// ================= mma.sync NT GEMM, 2 stages per barrier (6 buffers) ========
#define BM 128
#define BN 128
#define BKq 32
#define STAGE_BYTES 16384
#define NBUF 6
#define GEMM_SMEM (NBUF * STAGE_BYTES)   // 96 KB dynamic

__global__ __launch_bounds__(256, 2) void bgemm_nt(
    const bf16* __restrict__ A, const bf16* __restrict__ B,
    float* __restrict__ C, bf16* __restrict__ Cb,
    int K, int lda, int ldb, int ldc,
    long aZ, long bZ, long cZ,
    const float* __restrict__ bias, long biasZ,
    const float* __restrict__ res, int ldr,
    float scale)
{
    const int z = blockIdx.z;
    A += (long)z * aZ;
    B += (long)z * bZ;
    if (C)  C  += (long)z * cZ;
    if (Cb) Cb += (long)z * cZ;
    if (bias) bias += (long)z * biasZ;

    extern __shared__ __align__(128) unsigned char sm[];
    const uint32_t smBase = (uint32_t)__cvta_generic_to_shared(sm);

    const int tid  = threadIdx.x;
    const int wid  = tid >> 5;
    const int lane = tid & 31;
    const int wm = (wid & 1) * 64;
    const int wn = (wid >> 1) * 32;

    const long m0g = (long)blockIdx.y * BM;
    const long n0g = (long)blockIdx.x * BN;

    const int rowA = tid >> 2;
    const int cA   = tid & 3;
    const uint32_t aOff = rowA * 64 + ((cA ^ ((rowA >> 1) & 3)) * 16);
    const bf16* gA0 = A + (m0g + rowA) * (long)lda + cA * 8;
    const bf16* gA1 = gA0 + 64 * (long)lda;
    const bf16* gB0 = B + (n0g + rowA) * (long)ldb + cA * 8;
    const bf16* gB1 = gB0 + 64 * (long)ldb;

    // one stage = BK=32 slice into buffer (st % NBUF); no commit here
    auto ldg1 = [&](int st) {
        const int k0 = st * BKq;
        uint32_t aSt = smBase + (st % NBUF) * STAGE_BYTES;
        uint32_t bSt = aSt + 8192;
        cp16(aSt + aOff,        gA0 + k0);
        cp16(aSt + aOff + 4096, gA1 + k0);
        cp16(bSt + aOff,        gB0 + k0);
        cp16(bSt + aOff + 4096, gB1 + k0);
    };
    // one GROUP = 2 stages, single commit
    auto ldg2 = [&](int grp) {
        ldg1(2 * grp);
        ldg1(2 * grp + 1);
        CP_COMMIT();
    };

    const int q = lane >> 3, r = lane & 7;
    const int aRowBase = wm + ((q & 1) << 3) + r;
    const int pa = (aRowBase >> 1) & 3;
    const int bRowBase = wn + ((q >> 1) << 3) + r;
    const int pb = (bRowBase >> 1) & 3;

    float acc[4][4][4];
    #pragma unroll
    for (int i = 0; i < 4; i++)
        #pragma unroll
        for (int j = 0; j < 4; j++)
            #pragma unroll
            for (int t = 0; t < 4; t++) acc[i][j][t] = 0.0f;

    auto compute = [&](int buf) {
        uint32_t aSt = smBase + buf * STAGE_BYTES;
        uint32_t bSt = aSt + 8192;
        #pragma unroll
        for (int ks = 0; ks < 2; ks++) {
            uint32_t a[4][4];
            #pragma unroll
            for (int mt = 0; mt < 4; mt++) {
                uint32_t addr = aSt + (aRowBase + mt * 16) * 64 +
                                (((ks * 2 + (q >> 1)) ^ pa) * 16);
                LDSM4(a[mt][0], a[mt][1], a[mt][2], a[mt][3], addr);
            }
            uint32_t b[4][2];
            #pragma unroll
            for (int ntp = 0; ntp < 2; ntp++) {
                uint32_t addr = bSt + (bRowBase + ntp * 16) * 64 +
                                (((ks * 2 + (q & 1)) ^ pb) * 16);
                LDSM4(b[2*ntp][0], b[2*ntp][1], b[2*ntp+1][0], b[2*ntp+1][1], addr);
            }
            #pragma unroll
            for (int mt = 0; mt < 4; mt++)
                #pragma unroll
                for (int nt = 0; nt < 4; nt++)
                    mma_bf16(acc[mt][nt], a[mt][0], a[mt][1], a[mt][2], a[mt][3],
                             b[nt][0], b[nt][1]);
        }
    };

    // main loop over groups of 2 stages: 1 barrier per group (half the syncs)
    const int nG = K / (2 * BKq);
    ldg2(0);
    ldg2(1);
    for (int gI = 0; gI < nG; gI++) {
        CP_WAIT1();            // group gI's data has arrived
        __syncthreads();       // + all warps done computing group gI-1 (frees its pair)
        if (gI + 2 < nG) ldg2(gI + 2);   // writes the pair computed in gI-1
        compute((2 * gI)     % NBUF);
        compute((2 * gI + 1) % NBUF);
    }

    const int g = lane >> 2, tig = lane & 3;
    #pragma unroll
    for (int mt = 0; mt < 4; mt++) {
        long r0 = m0g + wm + mt * 16 + g;
        long r1 = r0 + 8;
        #pragma unroll
        for (int nt = 0; nt < 4; nt++) {
            long c = n0g + wn + nt * 8 + 2 * tig;
            float v0 = acc[mt][nt][0] * scale;
            float v1 = acc[mt][nt][1] * scale;
            float v2 = acc[mt][nt][2] * scale;
            float v3 = acc[mt][nt][3] * scale;
            if (bias) {
                float b0 = bias[c], b1 = bias[c + 1];
                v0 += b0; v1 += b1; v2 += b0; v3 += b1;
            }
            if (res) {
                v0 += res[r0 * ldr + c];
                v1 += res[r0 * ldr + c + 1];
                v2 += res[r1 * ldr + c];
                v3 += res[r1 * ldr + c + 1];
            }
            if (C) {
                *(float2*)(C + r0 * ldc + c) = make_float2(v0, v1);
                *(float2*)(C + r1 * ldc + c) = make_float2(v2, v3);
            }
            if (Cb) {
                *(uint32_t*)(Cb + r0 * ldc + c) = pack_bf16(v0, v1);
                *(uint32_t*)(Cb + r1 * ldc + c) = pack_bf16(v2, v3);
            }
        }
    }
}

// ================= fused flash attention (best-known R13/R14 config) =========
#define FA_SMEM (32768 + 4 * 16384 + 8192)
#define NCHUNK (S / 64)

__global__ __launch_bounds__(256, 2) void flash_attn(
    const bf16* __restrict__ Qg, const bf16* __restrict__ Kg,
    const bf16* __restrict__ Vg, const float* __restrict__ tbg,
    bf16* __restrict__ ctx)
{
    extern __shared__ __align__(128) unsigned char fsm[];
    const uint32_t sb = (uint32_t)__cvta_generic_to_shared(fsm);
    const uint32_t qB  = sb;
    const uint32_t tbB = sb + 98304;
    const float2* tbS2 = (const float2*)(fsm + 98304);

    const int tid = threadIdx.x;
    const int w = tid >> 5, lane = tid & 31;
    const int q = lane >> 3, r = lane & 7;
    const int g = lane >> 2, tig = lane & 3;
    const int m0 = blockIdx.x * 128;
    const int h  = blockIdx.y;

    const bf16* Qp = Qg + h * D;
    const bf16* Kp = Kg + h * D;
    const bf16* Vp = Vg + h * D;
    const float* tbh = tbg + h * S;

    // ---- load Q tile + tb row (grouped with chunk 0) ----
    {
        int row = tid >> 1, half = tid & 1;
        const bf16* src = Qp + (long)(m0 + row) * E + half * 64;
        uint32_t dst = qB + row * 256;
        #pragma unroll
        for (int c = 0; c < 8; c++) {
            int ch = half * 8 + c;
            cp16(dst + ((ch ^ (row & 7)) * 16), src + c * 8);
        }
        cp16(tbB + tid * 32,      tbh + tid * 8);
        cp16(tbB + tid * 32 + 16, tbh + tid * 8 + 4);
    }

    auto ldkv = [&](int buf, int j) {
        uint32_t base = sb + 32768 + buf * 32768;
        const int half = tid & 1;
        int row  = (tid & 127) >> 1;
        const bf16* src = (tid < 128)
            ? (Kp + (long)(j * 64 + row) * E + half * 64)
            : (Vp + (long)(j * 64 + row) * E + half * 64);
        uint32_t dst = base + (tid < 128 ? 0 : 16384) + row * 256;
        #pragma unroll
        for (int c = 0; c < 8; c++) {
            int ch = half * 8 + c;
            cp16(dst + ((ch ^ (row & 7)) * 16), src + c * 8);
        }
    };

    ldkv(0, 0);
    CP_COMMIT();

    float o[16][4];
    #pragma unroll
    for (int i = 0; i < 16; i++)
        #pragma unroll
        for (int t = 0; t < 4; t++) o[i][t] = 0.0f;
    float rmax0 = -INFINITY, rmax1 = -INFINITY;
    float rsum0 = 0.0f, rsum1 = 0.0f;   // per-thread partials (reduced at end)

    const int aRow = w * 16 + ((q & 1) << 3) + r;

    for (int j = 0; j < NCHUNK; j++) {
        const int b = j & 1;
        CP_WAIT0();
        __syncthreads();
        if (j + 1 < NCHUNK) { ldkv(b ^ 1, j + 1); CP_COMMIT(); }

        const uint32_t kBuf = sb + 32768 + b * 32768;
        const uint32_t vBuf = kBuf + 16384;

        // ---- scores: S = Q K^T ----
        float sc[8][4];
        #pragma unroll
        for (int nf = 0; nf < 8; nf++)
            #pragma unroll
            for (int t = 0; t < 4; t++) sc[nf][t] = 0.0f;

        #pragma unroll
        for (int kc = 0; kc < 8; kc++) {
            uint32_t a0, a1, a2, a3;
            LDSM4(a0, a1, a2, a3,
                  qB + aRow * 256 + (((2 * kc + (q >> 1)) ^ r) * 16));
            #pragma unroll
            for (int ntg = 0; ntg < 4; ntg++) {
                uint32_t b0, b1, b2, b3;
                int nRow = ntg * 16 + ((q >> 1) << 3) + r;
                LDSM4(b0, b1, b2, b3,
                      kBuf + nRow * 256 + (((2 * kc + (q & 1)) ^ r) * 16));
                mma_bf16(sc[2 * ntg],     a0, a1, a2, a3, b0, b1);
                mma_bf16(sc[2 * ntg + 1], a0, a1, a2, a3, b2, b3);
            }
        }

        // ---- scale (base-2) + time bias + online softmax ----
        float mxn0 = rmax0, mxn1 = rmax1;
        #pragma unroll
        for (int nf = 0; nf < 8; nf++) {
            float2 t = tbS2[(j * 64 + nf * 8) / 2 + tig];   // LDS.64, pre-scaled
            sc[nf][0] = fmaf(sc[nf][0], SCALE2, t.x);
            sc[nf][1] = fmaf(sc[nf][1], SCALE2, t.y);
            sc[nf][2] = fmaf(sc[nf][2], SCALE2, t.x);
            sc[nf][3] = fmaf(sc[nf][3], SCALE2, t.y);
            mxn0 = fmaxf(mxn0, fmaxf(sc[nf][0], sc[nf][1]));
            mxn1 = fmaxf(mxn1, fmaxf(sc[nf][2], sc[nf][3]));
        }
        mxn0 = fmaxf(mxn0, __shfl_xor_sync(0xffffffffu, mxn0, 1));
        mxn0 = fmaxf(mxn0, __shfl_xor_sync(0xffffffffu, mxn0, 2));
        mxn1 = fmaxf(mxn1, __shfl_xor_sync(0xffffffffu, mxn1, 1));
        mxn1 = fmaxf(mxn1, __shfl_xor_sync(0xffffffffu, mxn1, 2));

        float f0 = ex2(rmax0 - mxn0);
        float f1 = ex2(rmax1 - mxn1);
        rmax0 = mxn0; rmax1 = mxn1;

        // per-thread local sums only — NO cross-lane reduction here
        float ls0 = 0.0f, ls1 = 0.0f;
        #pragma unroll
        for (int nf = 0; nf < 8; nf++) {
            sc[nf][0] = ex2(sc[nf][0] - mxn0);
            sc[nf][1] = ex2(sc[nf][1] - mxn0);
            sc[nf][2] = ex2(sc[nf][2] - mxn1);
            sc[nf][3] = ex2(sc[nf][3] - mxn1);
            ls0 += sc[nf][0] + sc[nf][1];
            ls1 += sc[nf][2] + sc[nf][3];
        }
        rsum0 = rsum0 * f0 + ls0;   // mxn is quad-uniform -> partials consistent
        rsum1 = rsum1 * f1 + ls1;

        #pragma unroll
        for (int nf2 = 0; nf2 < 16; nf2++) {
            o[nf2][0] *= f0; o[nf2][1] *= f0;
            o[nf2][2] *= f1; o[nf2][3] *= f1;
        }

        uint32_t pA[4][4];
        #pragma unroll
        for (int kc2 = 0; kc2 < 4; kc2++) {
            pA[kc2][0] = pack_bf16(sc[2 * kc2][0],     sc[2 * kc2][1]);
            pA[kc2][1] = pack_bf16(sc[2 * kc2][2],     sc[2 * kc2][3]);
            pA[kc2][2] = pack_bf16(sc[2 * kc2 + 1][0], sc[2 * kc2 + 1][1]);
            pA[kc2][3] = pack_bf16(sc[2 * kc2 + 1][2], sc[2 * kc2 + 1][3]);
        }

        // ---- O += P V ----
        #pragma unroll
        for (int kc2 = 0; kc2 < 4; kc2++) {
            int kRow = kc2 * 16 + ((q & 1) << 3) + r;
            #pragma unroll
            for (int ntg = 0; ntg < 8; ntg++) {
                uint32_t b0, b1, b2, b3;
                LDSM4T(b0, b1, b2, b3,
                       vBuf + kRow * 256 + ((((ntg << 1) + (q >> 1)) ^ r) * 16));
                mma_bf16(o[2 * ntg],     pA[kc2][0], pA[kc2][1], pA[kc2][2], pA[kc2][3], b0, b1);
                mma_bf16(o[2 * ntg + 1], pA[kc2][0], pA[kc2][1], pA[kc2][2], pA[kc2][3], b2, b3);
            }
        }
    }

    // ---- epilogue: quad-reduce deferred row sums, then normalize ----
    rsum0 += __shfl_xor_sync(0xffffffffu, rsum0, 1);
    rsum0 += __shfl_xor_sync(0xffffffffu, rsum0, 2);
    rsum1 += __shfl_xor_sync(0xffffffffu, rsum1, 1);
    rsum1 += __shfl_xor_sync(0xffffffffu, rsum1, 2);
    float i0 = 1.0f / rsum0, i1 = 1.0f / rsum1;
    long r0 = m0 + w * 16 + g;
    long r1 = r0 + 8;
    bf16* c0 = ctx + r0 * E + h * D;
    bf16* c1 = ctx + r1 * E + h * D;
    #pragma unroll
    for (int nf2 = 0; nf2 < 16; nf2++) {
        int col = nf2 * 8 + 2 * tig;
        *(uint32_t*)(c0 + col) = pack_bf16(o[nf2][0] * i0, o[nf2][1] * i0);
        *(uint32_t*)(c1 + col) = pack_bf16(o[nf2][2] * i1, o[nf2][3] * i1);
    }
}

// ---------------- time bias (writes tb * log2e) ------------------------------
__global__ __launch_bounds__(512) void time_bias_kernel(
    const float* __restrict__ te, const float* __restrict__ tpw,
    const float* __restrict__ tpb, float* __restrict__ tb)
{
    int s = blockIdx.x;
    int w = threadIdx.x >> 5, lane = threadIdx.x & 31;
    const float4* rr   = (const float4*)(te  + (long)s * E);
    const float4* wrow = (const float4*)(tpw + (long)w * E);
    float acc = 0.0f;
    for (int e = lane; e < E / 4; e += 32) {
        float4 a = rr[e], b = wrow[e];
        acc += a.x * b.x + a.y * b.y + a.z * b.z + a.w * b.w;
    }
    acc = warpReduceSum(acc);
    if (lane == 0) tb[w * S + s] = (acc + tpb[w]) * LOG2E;
}

// ---------------- LayerNorm --------------------------------------------------
__global__ __launch_bounds__(256) void layernorm_kernel(
    const float* __restrict__ x, const float* __restrict__ g,
    const float* __restrict__ b, float* __restrict__ out)
{
    const float* xr = x + (long)blockIdx.x * E;
    float*       yr = out + (long)blockIdx.x * E;
    int tid = threadIdx.x;
    float vals[8];
    float s = 0.0f, s2 = 0.0f;
    #pragma unroll
    for (int i = 0; i < 8; i++) {
        float v = xr[tid + i * 256];
        vals[i] = v;
        s += v;
        s2 += v * v;
    }
    s  = blockReduce256<false>(s);
    s2 = blockReduce256<false>(s2);
    float mean = s * (1.0f / E);
    float var  = s2 * (1.0f / E) - mean * mean;
    float rstd = rsqrtf(var + 1e-5f);
    #pragma unroll
    for (int i = 0; i < 8; i++) {
        int c = tid + i * 256;
        yr[c] = (vals[i] - mean) * rstd * g[c] + b[c];
    }
}

// ---------------- launch -----------------------------------------------------
extern "C" void kernel_launch(void* const* d_in, const int* in_sizes, int n_in,
                              void* d_out, int out_size)
{
    const float* query    = (const float*)d_in[0];
    const float* key      = (const float*)d_in[1];
    const float* value    = (const float*)d_in[2];
    const float* time_emb = (const float*)d_in[3];
    const float* in_w     = (const float*)d_in[4];
    const float* in_b     = (const float*)d_in[5];
    const float* out_w    = (const float*)d_in[6];
    const float* out_b    = (const float*)d_in[7];
    const float* tp_w     = (const float*)d_in[8];
    const float* tp_b     = (const float*)d_in[9];
    const float* ln_g     = (const float*)d_in[10];
    const float* ln_b     = (const float*)d_in[11];

    bf16 *in3, *wb, *owb, *QKV, *ctxb;
    float *tb, *x;
    cudaGetSymbolAddress((void**)&in3,  g_in3);
    cudaGetSymbolAddress((void**)&wb,   g_wb);
    cudaGetSymbolAddress((void**)&owb,  g_owb);
    cudaGetSymbolAddress((void**)&QKV,  g_QKV);
    cudaGetSymbolAddress((void**)&ctxb, g_ctxb);
    cudaGetSymbolAddress((void**)&tb,   g_tb);
    cudaGetSymbolAddress((void**)&x,    g_x);

    cudaFuncSetAttribute(flash_attn, cudaFuncAttributeMaxDynamicSharedMemorySize, FA_SMEM);
    cudaFuncSetAttribute(bgemm_nt,   cudaFuncAttributeMaxDynamicSharedMemorySize, GEMM_SMEM);

    // 0. one-time fp32 -> bf16 conversions: single exact-sized launch
    const int n4a = (L * E) / 4;
    const int n4w = (3 * E * E) / 4;
    const int n4o = (E * E) / 4;
    CvtJobs jobs;
    jobs.in[0] = (const float4*)query;  jobs.out[0] = (uint2*)in3;                  jobs.n4[0] = n4a;
    jobs.in[1] = (const float4*)key;    jobs.out[1] = (uint2*)(in3 + (long)L * E);  jobs.n4[1] = n4a;
    jobs.in[2] = (const float4*)value;  jobs.out[2] = (uint2*)(in3 + 2L * L * E);   jobs.n4[2] = n4a;
    jobs.in[3] = (const float4*)in_w;   jobs.out[3] = (uint2*)wb;                   jobs.n4[3] = n4w;
    jobs.in[4] = (const float4*)out_w;  jobs.out[4] = (uint2*)owb;                  jobs.n4[4] = n4o;
    jobs.off[0] = 0;
    jobs.off[1] = jobs.off[0] + (n4a + 1023) / 1024;
    jobs.off[2] = jobs.off[1] + (n4a + 1023) / 1024;
    jobs.off[3] = jobs.off[2] + (n4a + 1023) / 1024;
    jobs.off[4] = jobs.off[3] + (n4w + 1023) / 1024;
    jobs.off[5] = jobs.off[4] + (n4o + 1023) / 1024;
    cvt_multi<<<jobs.off[5], 256>>>(jobs);

    // 1. time bias (H x S), pre-scaled by log2e
    time_bias_kernel<<<S, 512>>>(time_emb, tp_w, tp_b, tb);

    // 2. Q,K,V projections in one launch (grid.z selects q/k/v)
    bf16* Qb = QKV;
    bf16* Kb = QKV + (long)L * E;
    bf16* Vb = QKV + 2L * L * E;
    dim3 gqkv(E / BN, L / BM, 3);
    bgemm_nt<<<gqkv, 256, GEMM_SMEM>>>(in3, wb, nullptr, QKV,
                                       E, E, E, E,
                                       (long)L * E, (long)E * E, (long)L * E,
                                       in_b, (long)E, nullptr, 0, 1.0f);

    // 3-5. fused attention (scores + time bias + softmax + PV)
    dim3 gfa(L / 128, H);
    flash_attn<<<gfa, 256, FA_SMEM>>>(Qb, Kb, Vb, tb, ctxb);

    // 6. out projection + residual (fp32 out)
    dim3 gop(E / BN, L / BM, 1);
    bgemm_nt<<<gop, 256, GEMM_SMEM>>>(ctxb, owb, x, nullptr,
                                      E, E, E, E, 0, 0, 0,
                                      out_b, 0, query, E, 1.0f);

    // 7. LayerNorm -> d_out
    layernorm_kernel<<<L, 256>>>(x, ln_g, ln_b, (float*)d_out);
}

// round 16
// speedup vs baseline: 1.0839x; 1.0743x over previous
#include <cuda_runtime.h>
#include <cuda_bf16.h>
#include <math.h>
#include <stdint.h>

// Problem constants
#define L 2048
#define S 2048
#define E 2048
#define H 16
#define D 128
#define SCALE 0.08838834764831843f      // 1/sqrt(128)
#define LOG2E 1.4426950408889634f
#define SCALE2 (SCALE * LOG2E)          // scale in base-2 domain

typedef __nv_bfloat16 bf16;

// ---------------- scratch (static device globals; no allocation) -------------
__device__ bf16  g_in3[3L * L * E];          // q,k,v inputs (bf16), stacked
__device__ bf16  g_wb[3L * E * E];           // in_proj weights bf16
__device__ bf16  g_owb[(long)E * E];         // out_proj weights bf16
__device__ bf16  g_QKV[3L * L * E];          // Q | K | V (each [L,E])
__device__ bf16  g_ctxb[(long)L * E];
__device__ float g_tb[H * S];                // time bias PRE-SCALED by log2(e)
__device__ float g_x[(long)L * E];

// ---------------- ptx helpers ------------------------------------------------
__device__ __forceinline__ uint32_t pack_bf16(float x, float y) {
    uint32_t u;
    asm("cvt.rn.bf16x2.f32 %0, %1, %2;" : "=r"(u) : "f"(y), "f"(x));
    return u;
}

__device__ __forceinline__ float ex2(float x) {
    float r;
    asm("ex2.approx.f32 %0, %1;" : "=f"(r) : "f"(x));
    return r;
}

__device__ __forceinline__ void mma_bf16(float c[4],
                                         uint32_t a0, uint32_t a1, uint32_t a2, uint32_t a3,
                                         uint32_t b0, uint32_t b1) {
    asm volatile(
        "mma.sync.aligned.m16n8k16.row.col.f32.bf16.bf16.f32 "
        "{%0,%1,%2,%3}, {%4,%5,%6,%7}, {%8,%9}, {%0,%1,%2,%3};\n"
        : "+f"(c[0]), "+f"(c[1]), "+f"(c[2]), "+f"(c[3])
        : "r"(a0), "r"(a1), "r"(a2), "r"(a3), "r"(b0), "r"(b1));
}

__device__ __forceinline__ void cp16(uint32_t dst, const void* src) {
    asm volatile("cp.async.cg.shared.global [%0], [%1], 16;" :: "r"(dst), "l"(src));
}
#define CP_COMMIT() asm volatile("cp.async.commit_group;")
#define CP_WAIT1()  asm volatile("cp.async.wait_group 1;")
#define CP_WAIT0()  asm volatile("cp.async.wait_group 0;")

#define LDSM4(r0, r1, r2, r3, addr)                                            \
    asm volatile("ldmatrix.sync.aligned.m8n8.x4.shared.b16 {%0,%1,%2,%3}, [%4];" \
                 : "=r"(r0), "=r"(r1), "=r"(r2), "=r"(r3) : "r"(addr))
#define LDSM4T(r0, r1, r2, r3, addr)                                           \
    asm volatile("ldmatrix.sync.aligned.m8n8.x4.trans.shared.b16 {%0,%1,%2,%3}, [%4];" \
                 : "=r"(r0), "=r"(r1), "=r"(r2), "=r"(r3) : "r"(addr))

__device__ __forceinline__ float warpReduceSum(float v) {
    #pragma unroll
    for (int o = 16; o > 0; o >>= 1) v += __shfl_xor_sync(0xffffffffu, v, o);
    return v;
}
template<bool MAX>
__device__ __forceinline__ float blockReduce256(float v) {
    __shared__ float sh[8];
    int lane = threadIdx.x & 31, wid = threadIdx.x >> 5;
    #pragma unroll
    for (int o = 16; o > 0; o >>= 1)
        v = MAX ? fmaxf(v, __shfl_xor_sync(0xffffffffu, v, o))
                : v + __shfl_xor_sync(0xffffffffu, v, o);
    if (lane == 0) sh[wid] = v;
    __syncthreads();
    if (wid == 0) {
        float t = (lane < 8) ? sh[lane] : (MAX ? -INFINITY : 0.0f);
        #pragma unroll
        for (int o = 4; o > 0; o >>= 1)
            t = MAX ? fmaxf(t, __shfl_xor_sync(0xffffffffu, t, o))
                    : t + __shfl_xor_sync(0xffffffffu, t, o);
        if (lane == 0) sh[0] = t;
    }
    __syncthreads();
    float r = sh[0];
    __syncthreads();
    return r;
}

// ---------------- fused prologue: 5 cvt jobs + time-bias job -----------------
// Blocks [0, off[5]): fp32->bf16 conversion jobs (exact-sized).
// Blocks [off[5], off[5]+S): time bias. Block s, warp w computes heads w, w+8.
struct ProJobs {
    const float4* in[5];
    uint2*        out[5];
    int           n4[5];
    int           off[6];
    const float*  te;     // time_emb [S,E]
    const float*  tpw;    // tp_w [H,E]
    const float*  tpb;    // tp_b [H]
    float*        tb;     // out [H,S], pre-scaled by log2e
};

__global__ __launch_bounds__(256) void prologue_multi(ProJobs jobs)
{
    const int b = blockIdx.x;
    const int lane = threadIdx.x & 31;
    const int wrp  = threadIdx.x >> 5;

    if (b >= jobs.off[5]) {
        // ---- time-bias path ----
        const int s = b - jobs.off[5];
        const float4* rr = (const float4*)(jobs.te + (long)s * E);
        #pragma unroll
        for (int hh = 0; hh < 2; hh++) {
            const int h = wrp + hh * 8;
            const float4* wrow = (const float4*)(jobs.tpw + (long)h * E);
            float acc = 0.0f;
            for (int e = lane; e < E / 4; e += 32) {
                float4 a = rr[e], w4 = wrow[e];
                acc += a.x * w4.x + a.y * w4.y + a.z * w4.z + a.w * w4.w;
            }
            acc = warpReduceSum(acc);
            if (lane == 0) jobs.tb[h * S + s] = (acc + jobs.tpb[h]) * LOG2E;
        }
        return;
    }

    // ---- conversion path ----
    int z = 0;
    #pragma unroll
    for (int k = 1; k < 5; k++) z += (b >= jobs.off[k]);
    const float4* __restrict__ in = jobs.in[z];
    uint2* __restrict__ out = jobs.out[z];
    const int n4 = jobs.n4[z];
    int i0 = (b - jobs.off[z]) * 1024 + threadIdx.x;
    float4 v[4];
    #pragma unroll
    for (int j = 0; j < 4; j++) {
        int i = i0 + j * 256;
        if (i < n4) v[j] = in[i];
    }
    #pragma unroll
    for (int j = 0; j < 4; j++) {
        int i = i0 + j * 256;
        if (i < n4)
            out[i] = make_uint2(pack_bf16(v[j].x, v[j].y), pack_bf16(v[j].z, v[j].w));
    }
}

// ================= mma.sync NT GEMM, 2 stages per barrier (6 buffers) ========
#define BM 128
#define BN 128
#define BKq 32
#define STAGE_BYTES 16384
#define NBUF 6
#define GEMM_SMEM (NBUF * STAGE_BYTES)   // 96 KB dynamic

__global__ __launch_bounds__(256, 2) void bgemm_nt(
    const bf16* __restrict__ A, const bf16* __restrict__ B,
    float* __restrict__ C, bf16* __restrict__ Cb,
    int K, int lda, int ldb, int ldc,
    long aZ, long bZ, long cZ,
    const float* __restrict__ bias, long biasZ,
    const float* __restrict__ res, int ldr,
    float scale)
{
    const int z = blockIdx.z;
    A += (long)z * aZ;
    B += (long)z * bZ;
    if (C)  C  += (long)z * cZ;
    if (Cb) Cb += (long)z * cZ;
    if (bias) bias += (long)z * biasZ;

    extern __shared__ __align__(128) unsigned char sm[];
    const uint32_t smBase = (uint32_t)__cvta_generic_to_shared(sm);

    const int tid  = threadIdx.x;
    const int wid  = tid >> 5;
    const int lane = tid & 31;
    const int wm = (wid & 1) * 64;
    const int wn = (wid >> 1) * 32;

    const long m0g = (long)blockIdx.y * BM;
    const long n0g = (long)blockIdx.x * BN;

    const int rowA = tid >> 2;
    const int cA   = tid & 3;
    const uint32_t aOff = rowA * 64 + ((cA ^ ((rowA >> 1) & 3)) * 16);
    const bf16* gA0 = A + (m0g + rowA) * (long)lda + cA * 8;
    const bf16* gA1 = gA0 + 64 * (long)lda;
    const bf16* gB0 = B + (n0g + rowA) * (long)ldb + cA * 8;
    const bf16* gB1 = gB0 + 64 * (long)ldb;

    auto ldg1 = [&](int st) {
        const int k0 = st * BKq;
        uint32_t aSt = smBase + (st % NBUF) * STAGE_BYTES;
        uint32_t bSt = aSt + 8192;
        cp16(aSt + aOff,        gA0 + k0);
        cp16(aSt + aOff + 4096, gA1 + k0);
        cp16(bSt + aOff,        gB0 + k0);
        cp16(bSt + aOff + 4096, gB1 + k0);
    };
    auto ldg2 = [&](int grp) {
        ldg1(2 * grp);
        ldg1(2 * grp + 1);
        CP_COMMIT();
    };

    const int q = lane >> 3, r = lane & 7;
    const int aRowBase = wm + ((q & 1) << 3) + r;
    const int pa = (aRowBase >> 1) & 3;
    const int bRowBase = wn + ((q >> 1) << 3) + r;
    const int pb = (bRowBase >> 1) & 3;

    float acc[4][4][4];
    #pragma unroll
    for (int i = 0; i < 4; i++)
        #pragma unroll
        for (int j = 0; j < 4; j++)
            #pragma unroll
            for (int t = 0; t < 4; t++) acc[i][j][t] = 0.0f;

    auto compute = [&](int buf) {
        uint32_t aSt = smBase + buf * STAGE_BYTES;
        uint32_t bSt = aSt + 8192;
        #pragma unroll
        for (int ks = 0; ks < 2; ks++) {
            uint32_t a[4][4];
            #pragma unroll
            for (int mt = 0; mt < 4; mt++) {
                uint32_t addr = aSt + (aRowBase + mt * 16) * 64 +
                                (((ks * 2 + (q >> 1)) ^ pa) * 16);
                LDSM4(a[mt][0], a[mt][1], a[mt][2], a[mt][3], addr);
            }
            uint32_t b[4][2];
            #pragma unroll
            for (int ntp = 0; ntp < 2; ntp++) {
                uint32_t addr = bSt + (bRowBase + ntp * 16) * 64 +
                                (((ks * 2 + (q & 1)) ^ pb) * 16);
                LDSM4(b[2*ntp][0], b[2*ntp][1], b[2*ntp+1][0], b[2*ntp+1][1], addr);
            }
            #pragma unroll
            for (int mt = 0; mt < 4; mt++)
                #pragma unroll
                for (int nt = 0; nt < 4; nt++)
                    mma_bf16(acc[mt][nt], a[mt][0], a[mt][1], a[mt][2], a[mt][3],
                             b[nt][0], b[nt][1]);
        }
    };

    const int nG = K / (2 * BKq);
    ldg2(0);
    ldg2(1);
    for (int gI = 0; gI < nG; gI++) {
        CP_WAIT1();
        __syncthreads();
        if (gI + 2 < nG) ldg2(gI + 2);
        compute((2 * gI)     % NBUF);
        compute((2 * gI + 1) % NBUF);
    }

    const int g = lane >> 2, tig = lane & 3;
    #pragma unroll
    for (int mt = 0; mt < 4; mt++) {
        long r0 = m0g + wm + mt * 16 + g;
        long r1 = r0 + 8;
        #pragma unroll
        for (int nt = 0; nt < 4; nt++) {
            long c = n0g + wn + nt * 8 + 2 * tig;
            float v0 = acc[mt][nt][0] * scale;
            float v1 = acc[mt][nt][1] * scale;
            float v2 = acc[mt][nt][2] * scale;
            float v3 = acc[mt][nt][3] * scale;
            if (bias) {
                float b0 = bias[c], b1 = bias[c + 1];
                v0 += b0; v1 += b1; v2 += b0; v3 += b1;
            }
            if (res) {
                v0 += res[r0 * ldr + c];
                v1 += res[r0 * ldr + c + 1];
                v2 += res[r1 * ldr + c];
                v3 += res[r1 * ldr + c + 1];
            }
            if (C) {
                *(float2*)(C + r0 * ldc + c) = make_float2(v0, v1);
                *(float2*)(C + r1 * ldc + c) = make_float2(v2, v3);
            }
            if (Cb) {
                *(uint32_t*)(Cb + r0 * ldc + c) = pack_bf16(v0, v1);
                *(uint32_t*)(Cb + r1 * ldc + c) = pack_bf16(v2, v3);
            }
        }
    }
}

// ================= fused flash attention (best-known R13/R14 config) =========
#define FA_SMEM (32768 + 4 * 16384 + 8192)
#define NCHUNK (S / 64)

__global__ __launch_bounds__(256, 2) void flash_attn(
    const bf16* __restrict__ Qg, const bf16* __restrict__ Kg,
    const bf16* __restrict__ Vg, const float* __restrict__ tbg,
    bf16* __restrict__ ctx)
{
    extern __shared__ __align__(128) unsigned char fsm[];
    const uint32_t sb = (uint32_t)__cvta_generic_to_shared(fsm);
    const uint32_t qB  = sb;
    const uint32_t tbB = sb + 98304;
    const float2* tbS2 = (const float2*)(fsm + 98304);

    const int tid = threadIdx.x;
    const int w = tid >> 5, lane = tid & 31;
    const int q = lane >> 3, r = lane & 7;
    const int g = lane >> 2, tig = lane & 3;
    const int m0 = blockIdx.x * 128;
    const int h  = blockIdx.y;

    const bf16* Qp = Qg + h * D;
    const bf16* Kp = Kg + h * D;
    const bf16* Vp = Vg + h * D;
    const float* tbh = tbg + h * S;

    // ---- load Q tile + tb row (grouped with chunk 0) ----
    {
        int row = tid >> 1, half = tid & 1;
        const bf16* src = Qp + (long)(m0 + row) * E + half * 64;
        uint32_t dst = qB + row * 256;
        #pragma unroll
        for (int c = 0; c < 8; c++) {
            int ch = half * 8 + c;
            cp16(dst + ((ch ^ (row & 7)) * 16), src + c * 8);
        }
        cp16(tbB + tid * 32,      tbh + tid * 8);
        cp16(tbB + tid * 32 + 16, tbh + tid * 8 + 4);
    }

    auto ldkv = [&](int buf, int j) {
        uint32_t base = sb + 32768 + buf * 32768;
        const int half = tid & 1;
        int row  = (tid & 127) >> 1;
        const bf16* src = (tid < 128)
            ? (Kp + (long)(j * 64 + row) * E + half * 64)
            : (Vp + (long)(j * 64 + row) * E + half * 64);
        uint32_t dst = base + (tid < 128 ? 0 : 16384) + row * 256;
        #pragma unroll
        for (int c = 0; c < 8; c++) {
            int ch = half * 8 + c;
            cp16(dst + ((ch ^ (row & 7)) * 16), src + c * 8);
        }
    };

    ldkv(0, 0);
    CP_COMMIT();

    float o[16][4];
    #pragma unroll
    for (int i = 0; i < 16; i++)
        #pragma unroll
        for (int t = 0; t < 4; t++) o[i][t] = 0.0f;
    float rmax0 = -INFINITY, rmax1 = -INFINITY;
    float rsum0 = 0.0f, rsum1 = 0.0f;   // per-thread partials (reduced at end)

    const int aRow = w * 16 + ((q & 1) << 3) + r;

    for (int j = 0; j < NCHUNK; j++) {
        const int b = j & 1;
        CP_WAIT0();
        __syncthreads();
        if (j + 1 < NCHUNK) { ldkv(b ^ 1, j + 1); CP_COMMIT(); }

        const uint32_t kBuf = sb + 32768 + b * 32768;
        const uint32_t vBuf = kBuf + 16384;

        // ---- scores: S = Q K^T ----
        float sc[8][4];
        #pragma unroll
        for (int nf = 0; nf < 8; nf++)
            #pragma unroll
            for (int t = 0; t < 4; t++) sc[nf][t] = 0.0f;

        #pragma unroll
        for (int kc = 0; kc < 8; kc++) {
            uint32_t a0, a1, a2, a3;
            LDSM4(a0, a1, a2, a3,
                  qB + aRow * 256 + (((2 * kc + (q >> 1)) ^ r) * 16));
            #pragma unroll
            for (int ntg = 0; ntg < 4; ntg++) {
                uint32_t b0, b1, b2, b3;
                int nRow = ntg * 16 + ((q >> 1) << 3) + r;
                LDSM4(b0, b1, b2, b3,
                      kBuf + nRow * 256 + (((2 * kc + (q & 1)) ^ r) * 16));
                mma_bf16(sc[2 * ntg],     a0, a1, a2, a3, b0, b1);
                mma_bf16(sc[2 * ntg + 1], a0, a1, a2, a3, b2, b3);
            }
        }

        // ---- scale (base-2) + time bias + online softmax ----
        float mxn0 = rmax0, mxn1 = rmax1;
        #pragma unroll
        for (int nf = 0; nf < 8; nf++) {
            float2 t = tbS2[(j * 64 + nf * 8) / 2 + tig];   // LDS.64, pre-scaled
            sc[nf][0] = fmaf(sc[nf][0], SCALE2, t.x);
            sc[nf][1] = fmaf(sc[nf][1], SCALE2, t.y);
            sc[nf][2] = fmaf(sc[nf][2], SCALE2, t.x);
            sc[nf][3] = fmaf(sc[nf][3], SCALE2, t.y);
            mxn0 = fmaxf(mxn0, fmaxf(sc[nf][0], sc[nf][1]));
            mxn1 = fmaxf(mxn1, fmaxf(sc[nf][2], sc[nf][3]));
        }
        mxn0 = fmaxf(mxn0, __shfl_xor_sync(0xffffffffu, mxn0, 1));
        mxn0 = fmaxf(mxn0, __shfl_xor_sync(0xffffffffu, mxn0, 2));
        mxn1 = fmaxf(mxn1, __shfl_xor_sync(0xffffffffu, mxn1, 1));
        mxn1 = fmaxf(mxn1, __shfl_xor_sync(0xffffffffu, mxn1, 2));

        float f0 = ex2(rmax0 - mxn0);
        float f1 = ex2(rmax1 - mxn1);
        rmax0 = mxn0; rmax1 = mxn1;

        float ls0 = 0.0f, ls1 = 0.0f;
        #pragma unroll
        for (int nf = 0; nf < 8; nf++) {
            sc[nf][0] = ex2(sc[nf][0] - mxn0);
            sc[nf][1] = ex2(sc[nf][1] - mxn0);
            sc[nf][2] = ex2(sc[nf][2] - mxn1);
            sc[nf][3] = ex2(sc[nf][3] - mxn1);
            ls0 += sc[nf][0] + sc[nf][1];
            ls1 += sc[nf][2] + sc[nf][3];
        }
        rsum0 = rsum0 * f0 + ls0;
        rsum1 = rsum1 * f1 + ls1;

        #pragma unroll
        for (int nf2 = 0; nf2 < 16; nf2++) {
            o[nf2][0] *= f0; o[nf2][1] *= f0;
            o[nf2][2] *= f1; o[nf2][3] *= f1;
        }

        uint32_t pA[4][4];
        #pragma unroll
        for (int kc2 = 0; kc2 < 4; kc2++) {
            pA[kc2][0] = pack_bf16(sc[2 * kc2][0],     sc[2 * kc2][1]);
            pA[kc2][1] = pack_bf16(sc[2 * kc2][2],     sc[2 * kc2][3]);
            pA[kc2][2] = pack_bf16(sc[2 * kc2 + 1][0], sc[2 * kc2 + 1][1]);
            pA[kc2][3] = pack_bf16(sc[2 * kc2 + 1][2], sc[2 * kc2 + 1][3]);
        }

        // ---- O += P V ----
        #pragma unroll
        for (int kc2 = 0; kc2 < 4; kc2++) {
            int kRow = kc2 * 16 + ((q & 1) << 3) + r;
            #pragma unroll
            for (int ntg = 0; ntg < 8; ntg++) {
                uint32_t b0, b1, b2, b3;
                LDSM4T(b0, b1, b2, b3,
                       vBuf + kRow * 256 + ((((ntg << 1) + (q >> 1)) ^ r) * 16));
                mma_bf16(o[2 * ntg],     pA[kc2][0], pA[kc2][1], pA[kc2][2], pA[kc2][3], b0, b1);
                mma_bf16(o[2 * ntg + 1], pA[kc2][0], pA[kc2][1], pA[kc2][2], pA[kc2][3], b2, b3);
            }
        }
    }

    // ---- epilogue: quad-reduce deferred row sums, then normalize ----
    rsum0 += __shfl_xor_sync(0xffffffffu, rsum0, 1);
    rsum0 += __shfl_xor_sync(0xffffffffu, rsum0, 2);
    rsum1 += __shfl_xor_sync(0xffffffffu, rsum1, 1);
    rsum1 += __shfl_xor_sync(0xffffffffu, rsum1, 2);
    float i0 = 1.0f / rsum0, i1 = 1.0f / rsum1;
    long r0 = m0 + w * 16 + g;
    long r1 = r0 + 8;
    bf16* c0 = ctx + r0 * E + h * D;
    bf16* c1 = ctx + r1 * E + h * D;
    #pragma unroll
    for (int nf2 = 0; nf2 < 16; nf2++) {
        int col = nf2 * 8 + 2 * tig;
        *(uint32_t*)(c0 + col) = pack_bf16(o[nf2][0] * i0, o[nf2][1] * i0);
        *(uint32_t*)(c1 + col) = pack_bf16(o[nf2][2] * i1, o[nf2][3] * i1);
    }
}

// ---------------- LayerNorm --------------------------------------------------
__global__ __launch_bounds__(256) void layernorm_kernel(
    const float* __restrict__ x, const float* __restrict__ g,
    const float* __restrict__ b, float* __restrict__ out)
{
    const float* xr = x + (long)blockIdx.x * E;
    float*       yr = out + (long)blockIdx.x * E;
    int tid = threadIdx.x;
    float vals[8];
    float s = 0.0f, s2 = 0.0f;
    #pragma unroll
    for (int i = 0; i < 8; i++) {
        float v = xr[tid + i * 256];
        vals[i] = v;
        s += v;
        s2 += v * v;
    }
    s  = blockReduce256<false>(s);
    s2 = blockReduce256<false>(s2);
    float mean = s * (1.0f / E);
    float var  = s2 * (1.0f / E) - mean * mean;
    float rstd = rsqrtf(var + 1e-5f);
    #pragma unroll
    for (int i = 0; i < 8; i++) {
        int c = tid + i * 256;
        yr[c] = (vals[i] - mean) * rstd * g[c] + b[c];
    }
}

// ---------------- launch -----------------------------------------------------
extern "C" void kernel_launch(void* const* d_in, const int* in_sizes, int n_in,
                              void* d_out, int out_size)
{
    const float* query    = (const float*)d_in[0];
    const float* key      = (const float*)d_in[1];
    const float* value    = (const float*)d_in[2];
    const float* time_emb = (const float*)d_in[3];
    const float* in_w     = (const float*)d_in[4];
    const float* in_b     = (const float*)d_in[5];
    const float* out_w    = (const float*)d_in[6];
    const float* out_b    = (const float*)d_in[7];
    const float* tp_w     = (const float*)d_in[8];
    const float* tp_b     = (const float*)d_in[9];
    const float* ln_g     = (const float*)d_in[10];
    const float* ln_b     = (const float*)d_in[11];

    bf16 *in3, *wb, *owb, *QKV, *ctxb;
    float *tb, *x;
    cudaGetSymbolAddress((void**)&in3,  g_in3);
    cudaGetSymbolAddress((void**)&wb,   g_wb);
    cudaGetSymbolAddress((void**)&owb,  g_owb);
    cudaGetSymbolAddress((void**)&QKV,  g_QKV);
    cudaGetSymbolAddress((void**)&ctxb, g_ctxb);
    cudaGetSymbolAddress((void**)&tb,   g_tb);
    cudaGetSymbolAddress((void**)&x,    g_x);

    cudaFuncSetAttribute(flash_attn, cudaFuncAttributeMaxDynamicSharedMemorySize, FA_SMEM);
    cudaFuncSetAttribute(bgemm_nt,   cudaFuncAttributeMaxDynamicSharedMemorySize, GEMM_SMEM);

    // 0. fused prologue: 5 cvt jobs + time bias in ONE launch
    const int n4a = (L * E) / 4;
    const int n4w = (3 * E * E) / 4;
    const int n4o = (E * E) / 4;
    ProJobs jobs;
    jobs.in[0] = (const float4*)query;  jobs.out[0] = (uint2*)in3;                  jobs.n4[0] = n4a;
    jobs.in[1] = (const float4*)key;    jobs.out[1] = (uint2*)(in3 + (long)L * E);  jobs.n4[1] = n4a;
    jobs.in[2] = (const float4*)value;  jobs.out[2] = (uint2*)(in3 + 2L * L * E);   jobs.n4[2] = n4a;
    jobs.in[3] = (const float4*)in_w;   jobs.out[3] = (uint2*)wb;                   jobs.n4[3] = n4w;
    jobs.in[4] = (const float4*)out_w;  jobs.out[4] = (uint2*)owb;                  jobs.n4[4] = n4o;
    jobs.off[0] = 0;
    jobs.off[1] = jobs.off[0] + (n4a + 1023) / 1024;
    jobs.off[2] = jobs.off[1] + (n4a + 1023) / 1024;
    jobs.off[3] = jobs.off[2] + (n4a + 1023) / 1024;
    jobs.off[4] = jobs.off[3] + (n4w + 1023) / 1024;
    jobs.off[5] = jobs.off[4] + (n4o + 1023) / 1024;
    jobs.te  = time_emb;
    jobs.tpw = tp_w;
    jobs.tpb = tp_b;
    jobs.tb  = tb;
    prologue_multi<<<jobs.off[5] + S, 256>>>(jobs);

    // 2. Q,K,V projections in one launch (grid.z selects q/k/v)
    bf16* Qb = QKV;
    bf16* Kb = QKV + (long)L * E;
    bf16* Vb = QKV + 2L * L * E;
    dim3 gqkv(E / BN, L / BM, 3);
    bgemm_nt<<<gqkv, 256, GEMM_SMEM>>>(in3, wb, nullptr, QKV,
                                       E, E, E, E,
                                       (long)L * E, (long)E * E, (long)L * E,
                                       in_b, (long)E, nullptr, 0, 1.0f);

    // 3-5. fused attention (scores + time bias + softmax + PV)
    dim3 gfa(L / 128, H);
    flash_attn<<<gfa, 256, FA_SMEM>>>(Qb, Kb, Vb, tb, ctxb);

    // 6. out projection + residual (fp32 out)
    dim3 gop(E / BN, L / BM, 1);
    bgemm_nt<<<gop, 256, GEMM_SMEM>>>(ctxb, owb, x, nullptr,
                                      E, E, E, E, 0, 0, 0,
                                      out_b, 0, query, E, 1.0f);

    // 7. LayerNorm -> d_out
    layernorm_kernel<<<L, 256>>>(x, ln_g, ln_b, (float*)d_out);
}